// round 13
// baseline (speedup 1.0000x reference)
#include <cuda_runtime.h>
#include <cuda_bf16.h>
#include <cstdint>

#define BN 16384
#define HN 128
#define PREDN 12

__device__ __forceinline__ uint32_t smem_u32(const void* p) {
    uint32_t a;
    asm("{ .reg .u64 t; cvta.to.shared.u64 t, %1; cvt.u32.u64 %0, t; }" : "=r"(a) : "l"(p));
    return a;
}

// blocked SW128 byte offset for [128 rows][128 bf16 cols] tile (8x64-bf16 atoms)
__device__ __forceinline__ int blk_off(int r, int c) {
    int boff = ((r >> 3) + (c >> 6) * 16) * 1024 + (r & 7) * 128 + (c & 63) * 2;
    return boff ^ ((boff >> 3) & 0x70);
}

__device__ __forceinline__ void ldsm4(uint32_t* r, uint32_t addr) {
    asm volatile("ldmatrix.sync.aligned.m8n8.x4.shared.b16 {%0,%1,%2,%3}, [%4];"
                 : "=r"(r[0]), "=r"(r[1]), "=r"(r[2]), "=r"(r[3]) : "r"(addr));
}
__device__ __forceinline__ void mma16816(float* c, const uint32_t* a, const uint32_t* b) {
    asm volatile(
        "mma.sync.aligned.m16n8k16.row.col.f32.bf16.bf16.f32 "
        "{%0,%1,%2,%3}, {%4,%5,%6,%7}, {%8,%9}, {%0,%1,%2,%3};"
        : "+f"(c[0]), "+f"(c[1]), "+f"(c[2]), "+f"(c[3])
        : "r"(a[0]), "r"(a[1]), "r"(a[2]), "r"(a[3]), "r"(b[0]), "r"(b[1]));
}
#define CP_ASYNC16(dst, src) \
    asm volatile("cp.async.cg.shared.global [%0], [%1], 16;" :: "r"(dst), "l"(src))
#define CP_COMMIT asm volatile("cp.async.commit_group;" ::: "memory")
#define CP_WAIT1 asm volatile("cp.async.wait_group 1;" ::: "memory")
#define CP_WAIT0 asm volatile("cp.async.wait_group 0;" ::: "memory")

// ==================== device scratch ====================
__device__ __align__(16) unsigned short g_WpHi[4][16384]; // bf16 hi, [n 128][k 128] swizzled per chunk
__device__ __align__(16) unsigned short g_WpLo[4][16384]; // bf16 lo
__device__ float g_Mc[2 * 512];
__device__ float g_bv[512];
__device__ float g_W1[128 * 64];
__device__ float g_h[BN * HN];      // row-major [row][128]
__device__ float g_c[BN * HN];      // COLUMN-major [u][BN]
__device__ float g_hpre[BN * HN];   // COLUMN-major [k][BN]
__device__ float g_gls[PREDN * BN];

// ==================== setup ====================
__global__ void setup_kernel(const float* __restrict__ W_emb, const float* __restrict__ b_emb,
                             const float* __restrict__ W_ih, const float* __restrict__ W_hh,
                             const float* __restrict__ b_ih, const float* __restrict__ b_hh,
                             const float* __restrict__ w1) {
    int idx = blockIdx.x * 256 + threadIdx.x;
    if (idx < 128 * 512) {
        int k = idx >> 9, n = idx & 511;
        int u = n >> 2, g = n & 3;
        float v = W_hh[(g * 128 + u) * 128 + k];
        __nv_bfloat16 bh = __float2bfloat16(v);
        __nv_bfloat16 bl = __float2bfloat16(v - __bfloat162float(bh));
        int chunk = n >> 7, nr = n & 127;
        int sw = blk_off(nr, k);
        g_WpHi[chunk][sw >> 1] = __bfloat16_as_ushort(bh);
        g_WpLo[chunk][sw >> 1] = __bfloat16_as_ushort(bl);
    }
    if (idx < 128 * 64) {
        int c = idx >> 6, kf = idx & 63;
        int hd = kf >> 4, f = kf & 15;
        g_W1[idx] = w1[(hd * 128 + c) * 16 + f];
    }
    if (idx < 512) {
        int n = idx;
        int u = n >> 2, g = n & 3;
        int row = g * 128 + u;
        float m0 = 0.f, m1 = 0.f, bb = 0.f;
        for (int e = 0; e < 64; e++) {
            float wih = W_ih[row * 64 + e];
            m0 += W_emb[e] * wih;
            m1 += W_emb[64 + e] * wih;
            bb += b_emb[e] * wih;
        }
        g_Mc[n] = m0;
        g_Mc[512 + n] = m1;
        g_bv[n] = bb + b_ih[row] + b_hh[row];
    }
}

__global__ void init_kernel(const float* __restrict__ h0) {
    int i = blockIdx.x * 256 + threadIdx.x;
    if (i < BN * HN) { g_h[i] = h0[i]; g_c[i] = 0.f; }
}

__global__ void gls_kernel(const float* __restrict__ pred_goal, const float* __restrict__ W_goal,
                           const float* __restrict__ b_goal) {
    int gw = (blockIdx.x * 256 + threadIdx.x) >> 5;
    int lane = threadIdx.x & 31;
    if (gw >= PREDN * BN) return;
    float pg0 = pred_goal[gw * 2 + 0], pg1 = pred_goal[gw * 2 + 1];
    float z[4];
    float m = -1e30f;
#pragma unroll
    for (int q = 0; q < 4; q++) {
        int u = lane + q * 32;
        z[q] = pg0 * W_goal[u] + pg1 * W_goal[128 + u] + b_goal[u];
        m = fmaxf(m, z[q]);
    }
#pragma unroll
    for (int s = 16; s > 0; s >>= 1) m = fmaxf(m, __shfl_xor_sync(0xffffffffu, m, s));
    float sum = 0.f;
#pragma unroll
    for (int q = 0; q < 4; q++) sum += __expf(z[q] - m);
#pragma unroll
    for (int s = 16; s > 0; s >>= 1) sum += __shfl_xor_sync(0xffffffffu, sum, s);
    if (lane == 0) g_gls[gw] = m + __logf(sum);
}

// ==================== PERSISTENT mono-kernel: 12 steps of (LSTM + GAT) ====================
#define SM_AHI 0
#define SM_ALO 32768
#define SM_B0  65536
#define MONO_SMEM 196608
#define GAT_AS 0
#define GAT_BS 16896                 // As = 32*132*4 bytes
#define GAT_XS (16896 + 16384)       // Bs = 32*32*16; xS = 128*68*4 (ends 68096)

__global__ __launch_bounds__(512, 1) void mono_kernel(
        const float* __restrict__ action_real,
        const float* __restrict__ pred_goal,
        const float* __restrict__ W_goal,
        const float* __restrict__ b_goal,
        const float* __restrict__ a_src1,
        const float* __restrict__ a_dst1,
        const float* __restrict__ bias1,
        const float* __restrict__ w2,
        const float* __restrict__ a_src2,
        const float* __restrict__ a_dst2,
        const float* __restrict__ bias2,
        const float* __restrict__ W_pos,
        const float* __restrict__ b_pos,
        float* __restrict__ out) {
    extern __shared__ __align__(1024) char sm[];
    uint32_t sb = smem_u32(sm);
    int tid = threadIdx.x;
    int w = tid >> 5, lane = tid & 31;
    int m0 = blockIdx.x * 128;

    // lstm lane mapping
    int g = lane >> 2, q = lane & 3;
    int parity = q & 1, uloc = q >> 1;
    int wm = w >> 1, wn = w & 1;
    int rg = m0 + wm * 16 + g;
    int a_row = lane & 15;
    int a_khalf = (lane >> 4) * 8;
    int b_nloc = wn * 64 + (lane >> 4) * 8 + (lane & 7);
    int b_khalf = ((lane >> 3) & 1) * 8;

    // gat lane mapping (compute on tid<256 only)
    int tx = tid & 15, ty = (tid & 255) >> 4;

    for (int t = 0; t < PREDN; t++) {
        // =================== LSTM phase (all 512 threads) ===================
        {   // prefetch B chunk 0 (xS region from previous gat is dead — barrier passed)
            const char* srcH = (const char*)g_WpHi[0];
            const char* srcL = (const char*)g_WpLo[0];
            uint32_t dH = sb + SM_B0;
            uint32_t dL = dH + 32768;
#pragma unroll
            for (int it = 0; it < 4; it++) {
                int off = (it * 512 + tid) * 16;
                CP_ASYNC16(dH + off, srcH + off);
                CP_ASYNC16(dL + off, srcL + off);
            }
            CP_COMMIT;
        }

        // convert A = g_h tile to bf16 hi/lo swizzled
#pragma unroll
        for (int it = 0; it < 8; it++) {
            int idx = it * 512 + tid;
            int r = idx >> 5;
            int c4 = (idx & 31) * 4;
            float4 v = *reinterpret_cast<const float4*>(&g_h[(m0 + r) * 128 + c4]);
            float a[4] = {v.x, v.y, v.z, v.w};
            unsigned short hs[4], ls[4];
#pragma unroll
            for (int p = 0; p < 4; p++) {
                __nv_bfloat16 bh = __float2bfloat16(a[p]);
                __nv_bfloat16 bl = __float2bfloat16(a[p] - __bfloat162float(bh));
                hs[p] = __bfloat16_as_ushort(bh);
                ls[p] = __bfloat16_as_ushort(bl);
            }
            int sw = blk_off(r, c4);
            *reinterpret_cast<uint2*>(sm + SM_AHI + sw) =
                make_uint2((uint32_t)hs[0] | ((uint32_t)hs[1] << 16),
                           (uint32_t)hs[2] | ((uint32_t)hs[3] << 16));
            *reinterpret_cast<uint2*>(sm + SM_ALO + sw) =
                make_uint2((uint32_t)ls[0] | ((uint32_t)ls[1] << 16),
                           (uint32_t)ls[2] | ((uint32_t)ls[3] << 16));
        }

        float2 arr[2], pgr[2];
        float glr[2];
#pragma unroll
        for (int mt = 0; mt < 2; mt++) {
            int row = rg + mt * 8;
            arr[mt] = *reinterpret_cast<const float2*>(&action_real[((8 + t) * BN + row) * 2]);
            pgr[mt] = *reinterpret_cast<const float2*>(&pred_goal[(t * BN + row) * 2]);
            glr[mt] = g_gls[t * BN + row];
        }

        for (int nc = 0; nc < 4; nc++) {
            uint32_t bbase = sb + SM_B0 + (nc & 1) * 65536;
            if (nc < 3) {
                const char* srcH = (const char*)g_WpHi[nc + 1];
                const char* srcL = (const char*)g_WpLo[nc + 1];
                uint32_t dH = sb + SM_B0 + (((nc + 1) & 1) * 65536);
                uint32_t dL = dH + 32768;
#pragma unroll
                for (int it = 0; it < 4; it++) {
                    int off = (it * 512 + tid) * 16;
                    CP_ASYNC16(dH + off, srcH + off);
                    CP_ASYNC16(dL + off, srcL + off);
                }
                CP_COMMIT;
                CP_WAIT1;
            } else {
                CP_WAIT0;
            }
            __syncthreads();

            float acc[8][4];
#pragma unroll
            for (int j = 0; j < 8; j++)
#pragma unroll
                for (int p = 0; p < 4; p++) acc[j][p] = 0.f;

#pragma unroll
            for (int ks = 0; ks < 8; ks++) {
                int kc = ks * 16;
                uint32_t ahi[4], alo[4];
                uint32_t ad = sb + SM_AHI + blk_off(wm * 16 + a_row, kc + a_khalf);
                ldsm4(ahi, ad);
                ldsm4(alo, ad + 32768);
                uint32_t bhi[4][4], blo[4][4];
#pragma unroll
                for (int pr = 0; pr < 4; pr++) {
                    uint32_t bd = bbase + blk_off(b_nloc + pr * 16, kc + b_khalf);
                    ldsm4(bhi[pr], bd);
                    ldsm4(blo[pr], bd + 32768);
                }
#pragma unroll
                for (int nt = 0; nt < 8; nt++) {
                    int pr = nt >> 1, hf = (nt & 1) * 2;
                    mma16816(acc[nt], ahi, &bhi[pr][hf]);
                    mma16816(acc[nt], ahi, &blo[pr][hf]);
                    mma16816(acc[nt], alo, &bhi[pr][hf]);
                }
            }

#pragma unroll
            for (int nt = 0; nt < 8; nt++) {
                int u = nc * 32 + wn * 16 + nt * 2 + uloc;
                int n4 = u * 4;
                float4 mA = *reinterpret_cast<const float4*>(&g_Mc[n4]);
                float4 mB = *reinterpret_cast<const float4*>(&g_Mc[512 + n4]);
                float4 bv = *reinterpret_cast<const float4*>(&g_bv[n4]);
                float wga = W_goal[u], wgb = W_goal[128 + u], bgu = b_goal[u];
                float c0 = acc[nt][0], c1 = acc[nt][1], c2 = acc[nt][2], c3 = acc[nt][3];
                float x0 = __shfl_xor_sync(0xffffffffu, c0, 1);
                float x1 = __shfl_xor_sync(0xffffffffu, c1, 1);
                float x2 = __shfl_xor_sync(0xffffffffu, c2, 1);
                float x3 = __shfl_xor_sync(0xffffffffu, c3, 1);
#pragma unroll
                for (int mt = 0; mt < 2; mt++) {
                    float gi, gf, gg2, go;
                    if (parity == 0) {
                        gi = (mt == 0) ? c0 : c2; gf = (mt == 0) ? c1 : c3;
                        gg2 = (mt == 0) ? x0 : x2; go = (mt == 0) ? x1 : x3;
                    } else {
                        gi = (mt == 0) ? x0 : x2; gf = (mt == 0) ? x1 : x3;
                        gg2 = (mt == 0) ? c0 : c2; go = (mt == 0) ? c1 : c3;
                    }
                    int row = rg + mt * 8;
                    float ar0 = arr[mt].x, ar1 = arr[mt].y;
                    gi += ar0 * mA.x + ar1 * mB.x + bv.x;
                    gf += ar0 * mA.y + ar1 * mB.y + bv.y;
                    gg2 += ar0 * mA.z + ar1 * mB.z + bv.z;
                    go += ar0 * mA.w + ar1 * mB.w + bv.w;
                    float cold = g_c[u * BN + row];
                    float rf = __expf(-gf);
                    float ri = __expf(-gi);
                    float rg2 = __expf(-2.f * gg2);
                    float cn = __fdividef(cold, 1.f + rf)
                             + __fdividef(1.f - rg2, (1.f + ri) * (1.f + rg2));
                    float ro = __expf(-go);
                    float rc = __expf(-2.f * cn);
                    float es = __expf(pgr[mt].x * wga + pgr[mt].y * wgb + bgu - glr[mt]);
                    float hh = __fdividef(es * (1.f - rc), (1.f + ro) * (1.f + rc));
                    g_c[u * BN + row] = cn;
                    g_hpre[u * BN + row] = hh;
                }
            }
            __syncthreads();
        }

        // =================== GAT phase (loads: 512 thr; compute: tid<256) ===================
        float (*As)[132] = reinterpret_cast<float(*)[132]>(sm + GAT_AS);
        float4 (*Bs)[32] = reinterpret_cast<float4(*)[32]>(sm + GAT_BS);
        float (*xS)[68] = reinterpret_cast<float(*)[68]>(sm + GAT_XS);

        {   // phase 1: hpre @ W1 + heads attention + elu -> xS
            float acc[8][4];
#pragma unroll
            for (int i = 0; i < 8; i++)
#pragma unroll
                for (int j = 0; j < 4; j++) acc[i][j] = 0.f;

            for (int kc = 0; kc < 4; kc++) {
                int k0 = kc * 32;
                __syncthreads();
#pragma unroll
                for (int it = 0; it < 2; it++) {
                    int idx = it * 512 + tid;
                    int k = idx >> 5, rq = idx & 31;
                    *reinterpret_cast<float4*>(&As[k][rq * 4]) =
                        *reinterpret_cast<const float4*>(&g_hpre[(k0 + k) * BN + m0 + rq * 4]);
                }
                {
                    int k = tid >> 4, qq = tid & 15;
                    Bs[k][qq] = *reinterpret_cast<const float4*>(&g_W1[(k0 + k) * 64 + qq * 4]);
                }
                __syncthreads();
                if (tid < 256) {
#pragma unroll
                    for (int k = 0; k < 32; k++) {
                        float4 a0 = *reinterpret_cast<const float4*>(&As[k][ty * 8]);
                        float4 a1 = *reinterpret_cast<const float4*>(&As[k][ty * 8 + 4]);
                        float4 b = Bs[k][tx];
                        float av[8] = {a0.x, a0.y, a0.z, a0.w, a1.x, a1.y, a1.z, a1.w};
                        float bw[4] = {b.x, b.y, b.z, b.w};
#pragma unroll
                        for (int i = 0; i < 8; i++)
#pragma unroll
                            for (int j = 0; j < 4; j++) acc[i][j] += av[i] * bw[j];
                    }
                }
            }
            __syncthreads();

            if (tid < 256) {
                int hd = tx >> 2;
                int fb = (tx & 3) * 4;
                float asv[4], adv[4], b1v[4];
#pragma unroll
                for (int j = 0; j < 4; j++) {
                    asv[j] = a_src1[hd * 16 + fb + j];
                    adv[j] = a_dst1[hd * 16 + fb + j];
                    b1v[j] = bias1[fb + j];
                }
                float src[8], dst[8];
#pragma unroll
                for (int n = 0; n < 8; n++) {
                    float ps = 0.f, pd = 0.f;
#pragma unroll
                    for (int j = 0; j < 4; j++) { ps += acc[n][j] * asv[j]; pd += acc[n][j] * adv[j]; }
                    src[n] = ps; dst[n] = pd;
                }
#pragma unroll
                for (int off = 1; off <= 2; off <<= 1) {
#pragma unroll
                    for (int n = 0; n < 8; n++) {
                        src[n] += __shfl_xor_sync(0xffffffffu, src[n], off);
                        dst[n] += __shfl_xor_sync(0xffffffffu, dst[n], off);
                    }
                }
#pragma unroll
                for (int n = 0; n < 8; n++) {
                    float e[8], mx = -1e30f;
#pragma unroll
                    for (int m = 0; m < 8; m++) {
                        float z = src[n] + dst[m];
                        z = (z >= 0.f) ? z : 0.2f * z;
                        e[m] = z;
                        mx = fmaxf(mx, z);
                    }
                    float s = 0.f;
#pragma unroll
                    for (int m = 0; m < 8; m++) { e[m] = __expf(e[m] - mx); s += e[m]; }
                    float inv = __fdividef(1.f, s);
                    float o[4] = {0.f, 0.f, 0.f, 0.f};
#pragma unroll
                    for (int m = 0; m < 8; m++) {
                        float wgt = e[m] * inv;
#pragma unroll
                        for (int j = 0; j < 4; j++) o[j] += wgt * acc[m][j];
                    }
                    float4 xo;
                    float* xp = &xo.x;
#pragma unroll
                    for (int j = 0; j < 4; j++) {
                        float v = o[j] + b1v[j];
                        xp[j] = (v > 0.f) ? v : (__expf(v) - 1.f);
                    }
                    *reinterpret_cast<float4*>(&xS[ty * 8 + n][tx * 4]) = xo;
                }
            }
        }
        __syncthreads();

        {   // phase 2: xS @ w2 + group attention + h/out
            float acc[8][8];
#pragma unroll
            for (int i = 0; i < 8; i++)
#pragma unroll
                for (int j = 0; j < 8; j++) acc[i][j] = 0.f;

            for (int kc = 0; kc < 2; kc++) {
                int k0 = kc * 32;
                __syncthreads();
#pragma unroll
                for (int it = 0; it < 2; it++) {
                    int idx = it * 512 + tid;
                    int k = idx >> 5, qq = idx & 31;
                    Bs[k][qq] = *reinterpret_cast<const float4*>(&w2[(k0 + k) * 128 + qq * 4]);
                }
                __syncthreads();
                if (tid < 256) {
#pragma unroll
                    for (int kg = 0; kg < 8; kg++) {
                        float a4[8][4];
#pragma unroll
                        for (int i = 0; i < 8; i++) {
                            float4 v = *reinterpret_cast<const float4*>(&xS[ty * 8 + i][k0 + kg * 4]);
                            a4[i][0] = v.x; a4[i][1] = v.y; a4[i][2] = v.z; a4[i][3] = v.w;
                        }
#pragma unroll
                        for (int kk = 0; kk < 4; kk++) {
                            float4 b0 = Bs[kg * 4 + kk][tx * 2], b1 = Bs[kg * 4 + kk][tx * 2 + 1];
                            float bw[8] = {b0.x, b0.y, b0.z, b0.w, b1.x, b1.y, b1.z, b1.w};
#pragma unroll
                            for (int i = 0; i < 8; i++)
#pragma unroll
                                for (int j = 0; j < 8; j++) acc[i][j] += a4[i][kk] * bw[j];
                        }
                    }
                }
            }

            if (tid < 256) {
                int o0 = tx * 8;
                float asv[8], adv[8], b2v[8], wp0[8], wp1[8];
#pragma unroll
                for (int j = 0; j < 8; j++) {
                    asv[j] = a_src2[o0 + j];
                    adv[j] = a_dst2[o0 + j];
                    b2v[j] = bias2[o0 + j];
                    wp0[j] = W_pos[(o0 + j) * 2 + 0];
                    wp1[j] = W_pos[(o0 + j) * 2 + 1];
                }
                float src[8], dst[8];
#pragma unroll
                for (int n = 0; n < 8; n++) {
                    float ps = 0.f, pd = 0.f;
#pragma unroll
                    for (int j = 0; j < 8; j++) { ps += acc[n][j] * asv[j]; pd += acc[n][j] * adv[j]; }
                    src[n] = ps; dst[n] = pd;
                }
#pragma unroll
                for (int off = 1; off <= 8; off <<= 1) {
#pragma unroll
                    for (int n = 0; n < 8; n++) {
                        src[n] += __shfl_xor_sync(0xffffffffu, src[n], off);
                        dst[n] += __shfl_xor_sync(0xffffffffu, dst[n], off);
                    }
                }
#pragma unroll
                for (int n = 0; n < 8; n++) {
                    int row = m0 + ty * 8 + n;
                    float e[8], mx = -1e30f;
#pragma unroll
                    for (int m = 0; m < 8; m++) {
                        float z = src[n] + dst[m];
                        z = (z >= 0.f) ? z : 0.2f * z;
                        e[m] = z;
                        mx = fmaxf(mx, z);
                    }
                    float s = 0.f;
#pragma unroll
                    for (int m = 0; m < 8; m++) { e[m] = __expf(e[m] - mx); s += e[m]; }
                    float inv = __fdividef(1.f, s);
                    float o[8];
#pragma unroll
                    for (int j = 0; j < 8; j++) o[j] = b2v[j];
#pragma unroll
                    for (int m = 0; m < 8; m++) {
                        float wgt = e[m] * inv;
#pragma unroll
                        for (int j = 0; j < 8; j++) o[j] += wgt * acc[m][j];
                    }
                    *reinterpret_cast<float4*>(&g_h[row * 128 + o0]) = make_float4(o[0], o[1], o[2], o[3]);
                    *reinterpret_cast<float4*>(&g_h[row * 128 + o0 + 4]) = make_float4(o[4], o[5], o[6], o[7]);
                    float p0 = 0.f, p1 = 0.f;
#pragma unroll
                    for (int j = 0; j < 8; j++) { p0 += o[j] * wp0[j]; p1 += o[j] * wp1[j]; }
#pragma unroll
                    for (int off = 1; off <= 8; off <<= 1) {
                        p0 += __shfl_xor_sync(0xffffffffu, p0, off);
                        p1 += __shfl_xor_sync(0xffffffffu, p1, off);
                    }
                    if (tx == 0) {
                        out[(t * BN + row) * 2 + 0] = p0 + b_pos[0];
                        out[(t * BN + row) * 2 + 1] = p1 + b_pos[1];
                    }
                }
            }
        }
        __syncthreads();   // g_h visible; smem free for next step's lstm
    }
}

extern "C" void kernel_launch(void* const* d_in, const int* in_sizes, int n_in,
                              void* d_out, int out_size) {
    const float* action_real = (const float*)d_in[0];
    const float* h0          = (const float*)d_in[1];
    const float* pred_goal   = (const float*)d_in[2];
    const float* W_emb  = (const float*)d_in[5];
    const float* b_emb  = (const float*)d_in[6];
    const float* W_ih   = (const float*)d_in[7];
    const float* W_hh   = (const float*)d_in[8];
    const float* b_ih   = (const float*)d_in[9];
    const float* b_hh   = (const float*)d_in[10];
    const float* W_goal = (const float*)d_in[11];
    const float* b_goal = (const float*)d_in[12];
    const float* w1     = (const float*)d_in[13];
    const float* a_src1 = (const float*)d_in[14];
    const float* a_dst1 = (const float*)d_in[15];
    const float* bias1  = (const float*)d_in[16];
    const float* w2     = (const float*)d_in[17];
    const float* a_src2 = (const float*)d_in[18];
    const float* a_dst2 = (const float*)d_in[19];
    const float* bias2  = (const float*)d_in[20];
    const float* W_pos  = (const float*)d_in[21];
    const float* b_pos  = (const float*)d_in[22];
    float* out = (float*)d_out;

    cudaFuncSetAttribute(mono_kernel, cudaFuncAttributeMaxDynamicSharedMemorySize, MONO_SMEM);

    setup_kernel<<<256, 256>>>(W_emb, b_emb, W_ih, W_hh, b_ih, b_hh, w1);
    init_kernel<<<(BN * HN + 255) / 256, 256>>>(h0);
    gls_kernel<<<(PREDN * BN * 32 + 255) / 256, 256>>>(pred_goal, W_goal, b_goal);

    mono_kernel<<<128, 512, MONO_SMEM>>>(action_real, pred_goal, W_goal, b_goal,
                                         a_src1, a_dst1, bias1, w2, a_src2, a_dst2,
                                         bias2, W_pos, b_pos, out);
}

// round 14
// speedup vs baseline: 1.0845x; 1.0845x over previous
#include <cuda_runtime.h>
#include <cuda_bf16.h>
#include <cstdint>

#define BN 16384
#define HN 128
#define PREDN 12

__device__ __forceinline__ uint32_t smem_u32(const void* p) {
    uint32_t a;
    asm("{ .reg .u64 t; cvta.to.shared.u64 t, %1; cvt.u32.u64 %0, t; }" : "=r"(a) : "l"(p));
    return a;
}

// blocked SW128 byte offset for [128 rows][128 bf16 cols] tile (8x64-bf16 atoms)
__device__ __forceinline__ int blk_off(int r, int c) {
    int boff = ((r >> 3) + (c >> 6) * 16) * 1024 + (r & 7) * 128 + (c & 63) * 2;
    return boff ^ ((boff >> 3) & 0x70);
}

__device__ __forceinline__ void ldsm4(uint32_t* r, uint32_t addr) {
    asm volatile("ldmatrix.sync.aligned.m8n8.x4.shared.b16 {%0,%1,%2,%3}, [%4];"
                 : "=r"(r[0]), "=r"(r[1]), "=r"(r[2]), "=r"(r[3]) : "r"(addr));
}
__device__ __forceinline__ void mma16816(float* c, const uint32_t* a, const uint32_t* b) {
    asm volatile(
        "mma.sync.aligned.m16n8k16.row.col.f32.bf16.bf16.f32 "
        "{%0,%1,%2,%3}, {%4,%5,%6,%7}, {%8,%9}, {%0,%1,%2,%3};"
        : "+f"(c[0]), "+f"(c[1]), "+f"(c[2]), "+f"(c[3])
        : "r"(a[0]), "r"(a[1]), "r"(a[2]), "r"(a[3]), "r"(b[0]), "r"(b[1]));
}
#define CP_ASYNC16(dst, src) \
    asm volatile("cp.async.cg.shared.global [%0], [%1], 16;" :: "r"(dst), "l"(src))
#define CP_COMMIT asm volatile("cp.async.commit_group;" ::: "memory")
#define CP_WAIT1 asm volatile("cp.async.wait_group 1;" ::: "memory")
#define CP_WAIT0 asm volatile("cp.async.wait_group 0;" ::: "memory")

// ==================== device scratch ====================
__device__ __align__(16) unsigned short g_WpHi[4][16384]; // bf16 hi, [n 128][k 128] swizzled per chunk
__device__ __align__(16) unsigned short g_WpLo[4][16384]; // bf16 lo
__device__ float g_Mc[2 * 512];
__device__ float g_bv[512];
__device__ float g_W1[128 * 64];
__device__ float g_h[BN * HN];      // row-major [row][128]
__device__ float g_c[BN * HN];      // COLUMN-major [u][BN]
__device__ float g_hpre[BN * HN];   // COLUMN-major [k][BN]
__device__ float g_gls[PREDN * BN];

// ==================== setup ====================
__global__ void setup_kernel(const float* __restrict__ W_emb, const float* __restrict__ b_emb,
                             const float* __restrict__ W_ih, const float* __restrict__ W_hh,
                             const float* __restrict__ b_ih, const float* __restrict__ b_hh,
                             const float* __restrict__ w1) {
    int idx = blockIdx.x * 256 + threadIdx.x;
    if (idx < 128 * 512) {
        int k = idx >> 9, n = idx & 511;
        int u = n >> 2, g = n & 3;
        float v = W_hh[(g * 128 + u) * 128 + k];
        __nv_bfloat16 bh = __float2bfloat16(v);
        __nv_bfloat16 bl = __float2bfloat16(v - __bfloat162float(bh));
        int chunk = n >> 7, nr = n & 127;
        int sw = blk_off(nr, k);
        g_WpHi[chunk][sw >> 1] = __bfloat16_as_ushort(bh);
        g_WpLo[chunk][sw >> 1] = __bfloat16_as_ushort(bl);
    }
    if (idx < 128 * 64) {
        int c = idx >> 6, kf = idx & 63;
        int hd = kf >> 4, f = kf & 15;
        g_W1[idx] = w1[(hd * 128 + c) * 16 + f];
    }
    if (idx < 512) {
        int n = idx;
        int u = n >> 2, g = n & 3;
        int row = g * 128 + u;
        float m0 = 0.f, m1 = 0.f, bb = 0.f;
        for (int e = 0; e < 64; e++) {
            float wih = W_ih[row * 64 + e];
            m0 += W_emb[e] * wih;
            m1 += W_emb[64 + e] * wih;
            bb += b_emb[e] * wih;
        }
        g_Mc[n] = m0;
        g_Mc[512 + n] = m1;
        g_bv[n] = bb + b_ih[row] + b_hh[row];
    }
}

__global__ void init_kernel(const float* __restrict__ h0) {
    int i = blockIdx.x * 256 + threadIdx.x;
    if (i < BN * HN) { g_h[i] = h0[i]; g_c[i] = 0.f; }
}

__global__ void gls_kernel(const float* __restrict__ pred_goal, const float* __restrict__ W_goal,
                           const float* __restrict__ b_goal) {
    int gw = (blockIdx.x * 256 + threadIdx.x) >> 5;
    int lane = threadIdx.x & 31;
    if (gw >= PREDN * BN) return;
    float pg0 = pred_goal[gw * 2 + 0], pg1 = pred_goal[gw * 2 + 1];
    float z[4];
    float m = -1e30f;
#pragma unroll
    for (int q = 0; q < 4; q++) {
        int u = lane + q * 32;
        z[q] = pg0 * W_goal[u] + pg1 * W_goal[128 + u] + b_goal[u];
        m = fmaxf(m, z[q]);
    }
#pragma unroll
    for (int s = 16; s > 0; s >>= 1) m = fmaxf(m, __shfl_xor_sync(0xffffffffu, m, s));
    float sum = 0.f;
#pragma unroll
    for (int q = 0; q < 4; q++) sum += __expf(z[q] - m);
#pragma unroll
    for (int s = 16; s > 0; s >>= 1) sum += __shfl_xor_sync(0xffffffffu, sum, s);
    if (lane == 0) g_gls[gw] = m + __logf(sum);
}

// ==================== LSTM via mma.sync bf16 split, 512 thr + cp.async ====================
#define SM_AHI 0
#define SM_ALO 32768
#define SM_B0  65536
#define LSTM_SMEM 196608

__global__ __launch_bounds__(512, 1) void lstm_mma(int t,
                                                   const float* __restrict__ action_real,
                                                   const float* __restrict__ pred_goal,
                                                   const float* __restrict__ W_goal,
                                                   const float* __restrict__ b_goal) {
    extern __shared__ __align__(1024) char sm[];
    uint32_t sb = smem_u32(sm);
    int tid = threadIdx.x;
    int w = tid >> 5, lane = tid & 31;
    int g = lane >> 2, q = lane & 3;
    int parity = q & 1, uloc = q >> 1;
    int wm = w >> 1, wn = w & 1;
    int m0 = blockIdx.x * 128;

    {   // prefetch B chunk 0
        const char* srcH = (const char*)g_WpHi[0];
        const char* srcL = (const char*)g_WpLo[0];
        uint32_t dH = sb + SM_B0;
        uint32_t dL = dH + 32768;
#pragma unroll
        for (int it = 0; it < 4; it++) {
            int off = (it * 512 + tid) * 16;
            CP_ASYNC16(dH + off, srcH + off);
            CP_ASYNC16(dL + off, srcL + off);
        }
        CP_COMMIT;
    }

    // convert A to bf16 hi/lo swizzled
#pragma unroll
    for (int it = 0; it < 8; it++) {
        int idx = it * 512 + tid;
        int r = idx >> 5;
        int c4 = (idx & 31) * 4;
        float4 v = *reinterpret_cast<const float4*>(&g_h[(m0 + r) * 128 + c4]);
        float a[4] = {v.x, v.y, v.z, v.w};
        unsigned short hs[4], ls[4];
#pragma unroll
        for (int p = 0; p < 4; p++) {
            __nv_bfloat16 bh = __float2bfloat16(a[p]);
            __nv_bfloat16 bl = __float2bfloat16(a[p] - __bfloat162float(bh));
            hs[p] = __bfloat16_as_ushort(bh);
            ls[p] = __bfloat16_as_ushort(bl);
        }
        int sw = blk_off(r, c4);
        *reinterpret_cast<uint2*>(sm + SM_AHI + sw) =
            make_uint2((uint32_t)hs[0] | ((uint32_t)hs[1] << 16),
                       (uint32_t)hs[2] | ((uint32_t)hs[3] << 16));
        *reinterpret_cast<uint2*>(sm + SM_ALO + sw) =
            make_uint2((uint32_t)ls[0] | ((uint32_t)ls[1] << 16),
                       (uint32_t)ls[2] | ((uint32_t)ls[3] << 16));
    }

    int rg = m0 + wm * 16 + g;
    float2 arr[2], pgr[2];
    float glr[2];
#pragma unroll
    for (int mt = 0; mt < 2; mt++) {
        int row = rg + mt * 8;
        arr[mt] = *reinterpret_cast<const float2*>(&action_real[((8 + t) * BN + row) * 2]);
        pgr[mt] = *reinterpret_cast<const float2*>(&pred_goal[(t * BN + row) * 2]);
        glr[mt] = g_gls[t * BN + row];
    }

    int a_row = lane & 15;
    int a_khalf = (lane >> 4) * 8;
    int b_nloc = wn * 64 + (lane >> 4) * 8 + (lane & 7);
    int b_khalf = ((lane >> 3) & 1) * 8;

    for (int nc = 0; nc < 4; nc++) {
        uint32_t bbase = sb + SM_B0 + (nc & 1) * 65536;
        if (nc < 3) {
            const char* srcH = (const char*)g_WpHi[nc + 1];
            const char* srcL = (const char*)g_WpLo[nc + 1];
            uint32_t dH = sb + SM_B0 + (((nc + 1) & 1) * 65536);
            uint32_t dL = dH + 32768;
#pragma unroll
            for (int it = 0; it < 4; it++) {
                int off = (it * 512 + tid) * 16;
                CP_ASYNC16(dH + off, srcH + off);
                CP_ASYNC16(dL + off, srcL + off);
            }
            CP_COMMIT;
            CP_WAIT1;
        } else {
            CP_WAIT0;
        }
        __syncthreads();

        float acc[8][4];
#pragma unroll
        for (int j = 0; j < 8; j++)
#pragma unroll
            for (int p = 0; p < 4; p++) acc[j][p] = 0.f;

#pragma unroll
        for (int ks = 0; ks < 8; ks++) {
            int kc = ks * 16;
            uint32_t ahi[4], alo[4];
            uint32_t ad = sb + SM_AHI + blk_off(wm * 16 + a_row, kc + a_khalf);
            ldsm4(ahi, ad);
            ldsm4(alo, ad + 32768);
            uint32_t bhi[4][4], blo[4][4];
#pragma unroll
            for (int pr = 0; pr < 4; pr++) {
                uint32_t bd = bbase + blk_off(b_nloc + pr * 16, kc + b_khalf);
                ldsm4(bhi[pr], bd);
                ldsm4(blo[pr], bd + 32768);
            }
#pragma unroll
            for (int nt = 0; nt < 8; nt++) {
                int pr = nt >> 1, hf = (nt & 1) * 2;
                mma16816(acc[nt], ahi, &bhi[pr][hf]);
                mma16816(acc[nt], ahi, &blo[pr][hf]);
                mma16816(acc[nt], alo, &bhi[pr][hf]);
            }
        }

        // ---- epilogue: pair-exchange gates, LSTM cell + goal gate ----
#pragma unroll
        for (int nt = 0; nt < 8; nt++) {
            int u = nc * 32 + wn * 16 + nt * 2 + uloc;
            int n4 = u * 4;
            float4 mA = *reinterpret_cast<const float4*>(&g_Mc[n4]);
            float4 mB = *reinterpret_cast<const float4*>(&g_Mc[512 + n4]);
            float4 bv = *reinterpret_cast<const float4*>(&g_bv[n4]);
            float wga = W_goal[u], wgb = W_goal[128 + u], bgu = b_goal[u];
            float c0 = acc[nt][0], c1 = acc[nt][1], c2 = acc[nt][2], c3 = acc[nt][3];
            float x0 = __shfl_xor_sync(0xffffffffu, c0, 1);
            float x1 = __shfl_xor_sync(0xffffffffu, c1, 1);
            float x2 = __shfl_xor_sync(0xffffffffu, c2, 1);
            float x3 = __shfl_xor_sync(0xffffffffu, c3, 1);
#pragma unroll
            for (int mt = 0; mt < 2; mt++) {
                float gi, gf, gg2, go;
                if (parity == 0) {
                    gi = (mt == 0) ? c0 : c2; gf = (mt == 0) ? c1 : c3;
                    gg2 = (mt == 0) ? x0 : x2; go = (mt == 0) ? x1 : x3;
                } else {
                    gi = (mt == 0) ? x0 : x2; gf = (mt == 0) ? x1 : x3;
                    gg2 = (mt == 0) ? c0 : c2; go = (mt == 0) ? c1 : c3;
                }
                int row = rg + mt * 8;
                float ar0 = arr[mt].x, ar1 = arr[mt].y;
                gi += ar0 * mA.x + ar1 * mB.x + bv.x;
                gf += ar0 * mA.y + ar1 * mB.y + bv.y;
                gg2 += ar0 * mA.z + ar1 * mB.z + bv.z;
                go += ar0 * mA.w + ar1 * mB.w + bv.w;
                float cold = g_c[u * BN + row];
                float rf = __expf(-gf);
                float ri = __expf(-gi);
                float rg2 = __expf(-2.f * gg2);
                float cn = __fdividef(cold, 1.f + rf)
                         + __fdividef(1.f - rg2, (1.f + ri) * (1.f + rg2));
                float ro = __expf(-go);
                float rc = __expf(-2.f * cn);
                float es = __expf(pgr[mt].x * wga + pgr[mt].y * wgb + bgu - glr[mt]);
                float hh = __fdividef(es * (1.f - rc), (1.f + ro) * (1.f + rc));
                g_c[u * BN + row] = cn;
                g_hpre[u * BN + row] = hh;
            }
        }
        __syncthreads();
    }
}

// ==================== GAT: 512 threads, warp = one group (column split) ====================
// smem: As 32*132*4 = 16896 | Bs 32*128*4 = 16384 | xS 128*68*4 = 34816 => 68096
#define GAT_AS 0
#define GAT_BS 16896
#define GAT_XS (16896 + 16384)
#define GAT_SMEM (16896 + 16384 + 34816)

__global__ __launch_bounds__(512, 1) void gat512c(int t,
                                                  const float* __restrict__ a_src1,
                                                  const float* __restrict__ a_dst1,
                                                  const float* __restrict__ bias1,
                                                  const float* __restrict__ w2,
                                                  const float* __restrict__ a_src2,
                                                  const float* __restrict__ a_dst2,
                                                  const float* __restrict__ bias2,
                                                  const float* __restrict__ W_pos,
                                                  const float* __restrict__ b_pos,
                                                  float* __restrict__ out) {
    extern __shared__ __align__(16) char smc[];
    float (*As)[132] = reinterpret_cast<float(*)[132]>(smc + GAT_AS);
    float* Bs = reinterpret_cast<float*>(smc + GAT_BS);     // flat [32][64 or 128]
    float (*xS)[68] = reinterpret_cast<float(*)[68]>(smc + GAT_XS);

    int tid = threadIdx.x;
    int w = tid >> 5, lane = tid & 31;   // warp w owns group rows m0+w*8 .. +7
    int m0 = blockIdx.x * 128;

    {   // ---- layer 1: hpre @ W1 ; each lane owns 2 cols (c = lane*2, +1) ----
        float acc[8][2];
#pragma unroll
        for (int i = 0; i < 8; i++) { acc[i][0] = 0.f; acc[i][1] = 0.f; }

        for (int kc = 0; kc < 4; kc++) {
            int k0 = kc * 32;
            __syncthreads();
#pragma unroll
            for (int it = 0; it < 2; it++) {
                int idx = it * 512 + tid;
                int k = idx >> 5, rq = idx & 31;
                *reinterpret_cast<float4*>(&As[k][rq * 4]) =
                    *reinterpret_cast<const float4*>(&g_hpre[(k0 + k) * BN + m0 + rq * 4]);
            }
            {   // W1 chunk: 32 rows x 64 floats = 512 float4
                int k = tid >> 4, qq = tid & 15;
                *reinterpret_cast<float4*>(&Bs[k * 64 + qq * 4]) =
                    *reinterpret_cast<const float4*>(&g_W1[(k0 + k) * 64 + qq * 4]);
            }
            __syncthreads();
#pragma unroll
            for (int k = 0; k < 32; k++) {
                float4 a0 = *reinterpret_cast<const float4*>(&As[k][w * 8]);
                float4 a1 = *reinterpret_cast<const float4*>(&As[k][w * 8 + 4]);
                float2 b = *reinterpret_cast<const float2*>(&Bs[k * 64 + lane * 2]);
                float av[8] = {a0.x, a0.y, a0.z, a0.w, a1.x, a1.y, a1.z, a1.w};
#pragma unroll
                for (int i = 0; i < 8; i++) {
                    acc[i][0] += av[i] * b.x;
                    acc[i][1] += av[i] * b.y;
                }
            }
        }

        int hd = lane >> 3;                // head = 16 cols = 8 lanes
        int fcol = (lane * 2) & 15;        // feature within head
        float as0 = a_src1[hd * 16 + fcol], as1 = a_src1[hd * 16 + fcol + 1];
        float ad0 = a_dst1[hd * 16 + fcol], ad1 = a_dst1[hd * 16 + fcol + 1];
        float b10 = bias1[fcol], b11 = bias1[fcol + 1];

        float src[8], dst[8];
#pragma unroll
        for (int n = 0; n < 8; n++) {
            src[n] = acc[n][0] * as0 + acc[n][1] * as1;
            dst[n] = acc[n][0] * ad0 + acc[n][1] * ad1;
        }
#pragma unroll
        for (int off = 1; off <= 4; off <<= 1) {
#pragma unroll
            for (int n = 0; n < 8; n++) {
                src[n] += __shfl_xor_sync(0xffffffffu, src[n], off);
                dst[n] += __shfl_xor_sync(0xffffffffu, dst[n], off);
            }
        }
        __syncthreads();   // As/Bs reads done; xS safe to write
#pragma unroll
        for (int n = 0; n < 8; n++) {
            float e[8], mx = -1e30f;
#pragma unroll
            for (int m = 0; m < 8; m++) {
                float z = src[n] + dst[m];
                z = (z >= 0.f) ? z : 0.2f * z;
                e[m] = z;
                mx = fmaxf(mx, z);
            }
            float s = 0.f;
#pragma unroll
            for (int m = 0; m < 8; m++) { e[m] = __expf(e[m] - mx); s += e[m]; }
            float inv = __fdividef(1.f, s);
            float o0 = 0.f, o1 = 0.f;
#pragma unroll
            for (int m = 0; m < 8; m++) {
                float wgt = e[m] * inv;
                o0 += wgt * acc[m][0];
                o1 += wgt * acc[m][1];
            }
            o0 += b10;
            o1 += b11;
            o0 = (o0 > 0.f) ? o0 : (__expf(o0) - 1.f);
            o1 = (o1 > 0.f) ? o1 : (__expf(o1) - 1.f);
            *reinterpret_cast<float2*>(&xS[w * 8 + n][lane * 2]) = make_float2(o0, o1);
        }
    }
    __syncthreads();

    {   // ---- layer 2: xS @ w2 ; each lane owns 4 cols (c = lane*4..+3) ----
        float acc[8][4];
#pragma unroll
        for (int i = 0; i < 8; i++)
#pragma unroll
            for (int j = 0; j < 4; j++) acc[i][j] = 0.f;

        for (int kc = 0; kc < 2; kc++) {
            int k0 = kc * 32;
            __syncthreads();
#pragma unroll
            for (int it = 0; it < 2; it++) {   // w2 chunk: 32 x 128 = 1024 float4
                int idx = it * 512 + tid;
                int k = idx >> 5, qq = idx & 31;
                *reinterpret_cast<float4*>(&Bs[k * 128 + qq * 4]) =
                    *reinterpret_cast<const float4*>(&w2[(k0 + k) * 128 + qq * 4]);
            }
            __syncthreads();
#pragma unroll
            for (int k = 0; k < 32; k++) {
                float4 b = *reinterpret_cast<const float4*>(&Bs[k * 128 + lane * 4]);
                float bw[4] = {b.x, b.y, b.z, b.w};
#pragma unroll
                for (int i = 0; i < 8; i++) {
                    float av = xS[w * 8 + i][k0 + k];
#pragma unroll
                    for (int j = 0; j < 4; j++) acc[i][j] += av * bw[j];
                }
            }
        }

        int o0c = lane * 4;
        float asv[4], adv[4], b2v[4], wp0[4], wp1[4];
#pragma unroll
        for (int j = 0; j < 4; j++) {
            asv[j] = a_src2[o0c + j];
            adv[j] = a_dst2[o0c + j];
            b2v[j] = bias2[o0c + j];
            wp0[j] = W_pos[(o0c + j) * 2 + 0];
            wp1[j] = W_pos[(o0c + j) * 2 + 1];
        }

        float src[8], dst[8];
#pragma unroll
        for (int n = 0; n < 8; n++) {
            float ps = 0.f, pd = 0.f;
#pragma unroll
            for (int j = 0; j < 4; j++) { ps += acc[n][j] * asv[j]; pd += acc[n][j] * adv[j]; }
            src[n] = ps; dst[n] = pd;
        }
#pragma unroll
        for (int off = 1; off <= 16; off <<= 1) {
#pragma unroll
            for (int n = 0; n < 8; n++) {
                src[n] += __shfl_xor_sync(0xffffffffu, src[n], off);
                dst[n] += __shfl_xor_sync(0xffffffffu, dst[n], off);
            }
        }
#pragma unroll
        for (int n = 0; n < 8; n++) {
            int row = m0 + w * 8 + n;
            float e[8], mx = -1e30f;
#pragma unroll
            for (int m = 0; m < 8; m++) {
                float z = src[n] + dst[m];
                z = (z >= 0.f) ? z : 0.2f * z;
                e[m] = z;
                mx = fmaxf(mx, z);
            }
            float s = 0.f;
#pragma unroll
            for (int m = 0; m < 8; m++) { e[m] = __expf(e[m] - mx); s += e[m]; }
            float inv = __fdividef(1.f, s);
            float o[4];
#pragma unroll
            for (int j = 0; j < 4; j++) o[j] = b2v[j];
#pragma unroll
            for (int m = 0; m < 8; m++) {
                float wgt = e[m] * inv;
#pragma unroll
                for (int j = 0; j < 4; j++) o[j] += wgt * acc[m][j];
            }
            *reinterpret_cast<float4*>(&g_h[row * 128 + o0c]) = make_float4(o[0], o[1], o[2], o[3]);
            float p0 = 0.f, p1 = 0.f;
#pragma unroll
            for (int j = 0; j < 4; j++) { p0 += o[j] * wp0[j]; p1 += o[j] * wp1[j]; }
#pragma unroll
            for (int off = 1; off <= 16; off <<= 1) {
                p0 += __shfl_xor_sync(0xffffffffu, p0, off);
                p1 += __shfl_xor_sync(0xffffffffu, p1, off);
            }
            if (lane == 0) {
                out[(t * BN + row) * 2 + 0] = p0 + b_pos[0];
                out[(t * BN + row) * 2 + 1] = p1 + b_pos[1];
            }
        }
    }
}

extern "C" void kernel_launch(void* const* d_in, const int* in_sizes, int n_in,
                              void* d_out, int out_size) {
    const float* action_real = (const float*)d_in[0];
    const float* h0          = (const float*)d_in[1];
    const float* pred_goal   = (const float*)d_in[2];
    const float* W_emb  = (const float*)d_in[5];
    const float* b_emb  = (const float*)d_in[6];
    const float* W_ih   = (const float*)d_in[7];
    const float* W_hh   = (const float*)d_in[8];
    const float* b_ih   = (const float*)d_in[9];
    const float* b_hh   = (const float*)d_in[10];
    const float* W_goal = (const float*)d_in[11];
    const float* b_goal = (const float*)d_in[12];
    const float* w1     = (const float*)d_in[13];
    const float* a_src1 = (const float*)d_in[14];
    const float* a_dst1 = (const float*)d_in[15];
    const float* bias1  = (const float*)d_in[16];
    const float* w2     = (const float*)d_in[17];
    const float* a_src2 = (const float*)d_in[18];
    const float* a_dst2 = (const float*)d_in[19];
    const float* bias2  = (const float*)d_in[20];
    const float* W_pos  = (const float*)d_in[21];
    const float* b_pos  = (const float*)d_in[22];
    float* out = (float*)d_out;

    cudaFuncSetAttribute(lstm_mma, cudaFuncAttributeMaxDynamicSharedMemorySize, LSTM_SMEM);
    cudaFuncSetAttribute(gat512c, cudaFuncAttributeMaxDynamicSharedMemorySize, GAT_SMEM);

    setup_kernel<<<256, 256>>>(W_emb, b_emb, W_ih, W_hh, b_ih, b_hh, w1);
    init_kernel<<<(BN * HN + 255) / 256, 256>>>(h0);
    gls_kernel<<<(PREDN * BN * 32 + 255) / 256, 256>>>(pred_goal, W_goal, b_goal);

    for (int t = 0; t < PREDN; t++) {
        lstm_mma<<<128, 512, LSTM_SMEM>>>(t, action_real, pred_goal, W_goal, b_goal);
        gat512c<<<128, 512, GAT_SMEM>>>(t, a_src1, a_dst1, bias1, w2, a_src2, a_dst2,
                                        bias2, W_pos, b_pos, out);
    }
}

// round 15
// speedup vs baseline: 1.1459x; 1.0566x over previous
#include <cuda_runtime.h>
#include <cuda_bf16.h>
#include <cstdint>

#define BN 16384
#define HN 128
#define PREDN 12

__device__ __forceinline__ uint32_t smem_u32(const void* p) {
    uint32_t a;
    asm("{ .reg .u64 t; cvta.to.shared.u64 t, %1; cvt.u32.u64 %0, t; }" : "=r"(a) : "l"(p));
    return a;
}

// blocked SW128 byte offset for [128 rows][128 bf16 cols] tile (8x64-bf16 atoms)
__device__ __forceinline__ int blk_off(int r, int c) {
    int boff = ((r >> 3) + (c >> 6) * 16) * 1024 + (r & 7) * 128 + (c & 63) * 2;
    return boff ^ ((boff >> 3) & 0x70);
}

__device__ __forceinline__ void ldsm4(uint32_t* r, uint32_t addr) {
    asm volatile("ldmatrix.sync.aligned.m8n8.x4.shared.b16 {%0,%1,%2,%3}, [%4];"
                 : "=r"(r[0]), "=r"(r[1]), "=r"(r[2]), "=r"(r[3]) : "r"(addr));
}
__device__ __forceinline__ void mma16816(float* c, const uint32_t* a, const uint32_t* b) {
    asm volatile(
        "mma.sync.aligned.m16n8k16.row.col.f32.bf16.bf16.f32 "
        "{%0,%1,%2,%3}, {%4,%5,%6,%7}, {%8,%9}, {%0,%1,%2,%3};"
        : "+f"(c[0]), "+f"(c[1]), "+f"(c[2]), "+f"(c[3])
        : "r"(a[0]), "r"(a[1]), "r"(a[2]), "r"(a[3]), "r"(b[0]), "r"(b[1]));
}
#define CP_ASYNC16(dst, src) \
    asm volatile("cp.async.cg.shared.global [%0], [%1], 16;" :: "r"(dst), "l"(src))
#define CP_COMMIT asm volatile("cp.async.commit_group;" ::: "memory")
#define CP_WAIT1 asm volatile("cp.async.wait_group 1;" ::: "memory")
#define CP_WAIT0 asm volatile("cp.async.wait_group 0;" ::: "memory")

// ==================== device scratch ====================
__device__ __align__(16) unsigned short g_WpHi[4][16384]; // bf16 hi, [n 128][k 128] swizzled per chunk
__device__ __align__(16) unsigned short g_WpLo[4][16384]; // bf16 lo
__device__ float g_Mc[2 * 512];
__device__ float g_bv[512];
__device__ float g_W1[128 * 64];
__device__ float g_h[BN * HN];      // row-major [row][128]
__device__ float g_c[BN * HN];      // COLUMN-major [u][BN]
__device__ float g_hpre[BN * HN];   // COLUMN-major [k][BN]
__device__ float g_gls[PREDN * BN];

// ==================== setup ====================
__global__ void setup_kernel(const float* __restrict__ W_emb, const float* __restrict__ b_emb,
                             const float* __restrict__ W_ih, const float* __restrict__ W_hh,
                             const float* __restrict__ b_ih, const float* __restrict__ b_hh,
                             const float* __restrict__ w1) {
    int idx = blockIdx.x * 256 + threadIdx.x;
    if (idx < 128 * 512) {
        int k = idx >> 9, n = idx & 511;
        int u = n >> 2, g = n & 3;
        float v = W_hh[(g * 128 + u) * 128 + k];
        __nv_bfloat16 bh = __float2bfloat16(v);
        __nv_bfloat16 bl = __float2bfloat16(v - __bfloat162float(bh));
        int chunk = n >> 7, nr = n & 127;
        int sw = blk_off(nr, k);
        g_WpHi[chunk][sw >> 1] = __bfloat16_as_ushort(bh);
        g_WpLo[chunk][sw >> 1] = __bfloat16_as_ushort(bl);
    }
    if (idx < 128 * 64) {
        int c = idx >> 6, kf = idx & 63;
        int hd = kf >> 4, f = kf & 15;
        g_W1[idx] = w1[(hd * 128 + c) * 16 + f];
    }
    if (idx < 512) {
        int n = idx;
        int u = n >> 2, g = n & 3;
        int row = g * 128 + u;
        float m0 = 0.f, m1 = 0.f, bb = 0.f;
        for (int e = 0; e < 64; e++) {
            float wih = W_ih[row * 64 + e];
            m0 += W_emb[e] * wih;
            m1 += W_emb[64 + e] * wih;
            bb += b_emb[e] * wih;
        }
        g_Mc[n] = m0;
        g_Mc[512 + n] = m1;
        g_bv[n] = bb + b_ih[row] + b_hh[row];
    }
}

__global__ void init_kernel(const float* __restrict__ h0) {
    int i = blockIdx.x * 256 + threadIdx.x;
    if (i < BN * HN) { g_h[i] = h0[i]; g_c[i] = 0.f; }
}

__global__ void gls_kernel(const float* __restrict__ pred_goal, const float* __restrict__ W_goal,
                           const float* __restrict__ b_goal) {
    int gw = (blockIdx.x * 256 + threadIdx.x) >> 5;
    int lane = threadIdx.x & 31;
    if (gw >= PREDN * BN) return;
    float pg0 = pred_goal[gw * 2 + 0], pg1 = pred_goal[gw * 2 + 1];
    float z[4];
    float m = -1e30f;
#pragma unroll
    for (int q = 0; q < 4; q++) {
        int u = lane + q * 32;
        z[q] = pg0 * W_goal[u] + pg1 * W_goal[128 + u] + b_goal[u];
        m = fmaxf(m, z[q]);
    }
#pragma unroll
    for (int s = 16; s > 0; s >>= 1) m = fmaxf(m, __shfl_xor_sync(0xffffffffu, m, s));
    float sum = 0.f;
#pragma unroll
    for (int q = 0; q < 4; q++) sum += __expf(z[q] - m);
#pragma unroll
    for (int s = 16; s > 0; s >>= 1) sum += __shfl_xor_sync(0xffffffffu, sum, s);
    if (lane == 0) g_gls[gw] = m + __logf(sum);
}

// ==================== PERSISTENT mono: 12 x (LSTM mma + GAT512c) ====================
#define SM_AHI 0
#define SM_ALO 32768
#define SM_B0  65536
#define MONO_SMEM 196608
// gat aliases (all < 68096, every reuse barrier-protected)
#define GAT_AS 0
#define GAT_BS 16896
#define GAT_XS (16896 + 16384)

__global__ __launch_bounds__(512, 1) void mono_kernel(
        const float* __restrict__ action_real,
        const float* __restrict__ pred_goal,
        const float* __restrict__ W_goal,
        const float* __restrict__ b_goal,
        const float* __restrict__ a_src1,
        const float* __restrict__ a_dst1,
        const float* __restrict__ bias1,
        const float* __restrict__ w2,
        const float* __restrict__ a_src2,
        const float* __restrict__ a_dst2,
        const float* __restrict__ bias2,
        const float* __restrict__ W_pos,
        const float* __restrict__ b_pos,
        float* __restrict__ out) {
    extern __shared__ __align__(1024) char sm[];
    uint32_t sb = smem_u32(sm);
    int tid = threadIdx.x;
    int w = tid >> 5, lane = tid & 31;
    int m0 = blockIdx.x * 128;

    // lstm lane mapping
    int g = lane >> 2, q = lane & 3;
    int parity = q & 1, uloc = q >> 1;
    int wm = w >> 1, wn = w & 1;
    int rg = m0 + wm * 16 + g;
    int a_row = lane & 15;
    int a_khalf = (lane >> 4) * 8;
    int b_nloc = wn * 64 + (lane >> 4) * 8 + (lane & 7);
    int b_khalf = ((lane >> 3) & 1) * 8;

    for (int t = 0; t < PREDN; t++) {
        // =================== PHASE 1: LSTM ===================
        {   // prefetch B chunk 0
            const char* srcH = (const char*)g_WpHi[0];
            const char* srcL = (const char*)g_WpLo[0];
            uint32_t dH = sb + SM_B0;
            uint32_t dL = dH + 32768;
#pragma unroll
            for (int it = 0; it < 4; it++) {
                int off = (it * 512 + tid) * 16;
                CP_ASYNC16(dH + off, srcH + off);
                CP_ASYNC16(dL + off, srcL + off);
            }
            CP_COMMIT;
        }

        // convert A to bf16 hi/lo swizzled
#pragma unroll
        for (int it = 0; it < 8; it++) {
            int idx = it * 512 + tid;
            int r = idx >> 5;
            int c4 = (idx & 31) * 4;
            float4 v = *reinterpret_cast<const float4*>(&g_h[(m0 + r) * 128 + c4]);
            float a[4] = {v.x, v.y, v.z, v.w};
            unsigned short hs[4], ls[4];
#pragma unroll
            for (int p = 0; p < 4; p++) {
                __nv_bfloat16 bh = __float2bfloat16(a[p]);
                __nv_bfloat16 bl = __float2bfloat16(a[p] - __bfloat162float(bh));
                hs[p] = __bfloat16_as_ushort(bh);
                ls[p] = __bfloat16_as_ushort(bl);
            }
            int sw = blk_off(r, c4);
            *reinterpret_cast<uint2*>(sm + SM_AHI + sw) =
                make_uint2((uint32_t)hs[0] | ((uint32_t)hs[1] << 16),
                           (uint32_t)hs[2] | ((uint32_t)hs[3] << 16));
            *reinterpret_cast<uint2*>(sm + SM_ALO + sw) =
                make_uint2((uint32_t)ls[0] | ((uint32_t)ls[1] << 16),
                           (uint32_t)ls[2] | ((uint32_t)ls[3] << 16));
        }

        float2 arr[2], pgr[2];
        float glr[2];
#pragma unroll
        for (int mt = 0; mt < 2; mt++) {
            int row = rg + mt * 8;
            arr[mt] = *reinterpret_cast<const float2*>(&action_real[((8 + t) * BN + row) * 2]);
            pgr[mt] = *reinterpret_cast<const float2*>(&pred_goal[(t * BN + row) * 2]);
            glr[mt] = g_gls[t * BN + row];
        }

        for (int nc = 0; nc < 4; nc++) {
            uint32_t bbase = sb + SM_B0 + (nc & 1) * 65536;
            if (nc < 3) {
                const char* srcH = (const char*)g_WpHi[nc + 1];
                const char* srcL = (const char*)g_WpLo[nc + 1];
                uint32_t dH = sb + SM_B0 + (((nc + 1) & 1) * 65536);
                uint32_t dL = dH + 32768;
#pragma unroll
                for (int it = 0; it < 4; it++) {
                    int off = (it * 512 + tid) * 16;
                    CP_ASYNC16(dH + off, srcH + off);
                    CP_ASYNC16(dL + off, srcL + off);
                }
                CP_COMMIT;
                CP_WAIT1;
            } else {
                CP_WAIT0;
            }
            __syncthreads();

            float acc[8][4];
#pragma unroll
            for (int j = 0; j < 8; j++)
#pragma unroll
                for (int p = 0; p < 4; p++) acc[j][p] = 0.f;

#pragma unroll
            for (int ks = 0; ks < 8; ks++) {
                int kc = ks * 16;
                uint32_t ahi[4], alo[4];
                uint32_t ad = sb + SM_AHI + blk_off(wm * 16 + a_row, kc + a_khalf);
                ldsm4(ahi, ad);
                ldsm4(alo, ad + 32768);
                uint32_t bhi[4][4], blo[4][4];
#pragma unroll
                for (int pr = 0; pr < 4; pr++) {
                    uint32_t bd = bbase + blk_off(b_nloc + pr * 16, kc + b_khalf);
                    ldsm4(bhi[pr], bd);
                    ldsm4(blo[pr], bd + 32768);
                }
#pragma unroll
                for (int nt = 0; nt < 8; nt++) {
                    int pr = nt >> 1, hf = (nt & 1) * 2;
                    mma16816(acc[nt], ahi, &bhi[pr][hf]);
                    mma16816(acc[nt], ahi, &blo[pr][hf]);
                    mma16816(acc[nt], alo, &bhi[pr][hf]);
                }
            }

#pragma unroll
            for (int nt = 0; nt < 8; nt++) {
                int u = nc * 32 + wn * 16 + nt * 2 + uloc;
                int n4 = u * 4;
                float4 mA = *reinterpret_cast<const float4*>(&g_Mc[n4]);
                float4 mB = *reinterpret_cast<const float4*>(&g_Mc[512 + n4]);
                float4 bv = *reinterpret_cast<const float4*>(&g_bv[n4]);
                float wga = W_goal[u], wgb = W_goal[128 + u], bgu = b_goal[u];
                float c0 = acc[nt][0], c1 = acc[nt][1], c2 = acc[nt][2], c3 = acc[nt][3];
                float x0 = __shfl_xor_sync(0xffffffffu, c0, 1);
                float x1 = __shfl_xor_sync(0xffffffffu, c1, 1);
                float x2 = __shfl_xor_sync(0xffffffffu, c2, 1);
                float x3 = __shfl_xor_sync(0xffffffffu, c3, 1);
#pragma unroll
                for (int mt = 0; mt < 2; mt++) {
                    float gi, gf, gg2, go;
                    if (parity == 0) {
                        gi = (mt == 0) ? c0 : c2; gf = (mt == 0) ? c1 : c3;
                        gg2 = (mt == 0) ? x0 : x2; go = (mt == 0) ? x1 : x3;
                    } else {
                        gi = (mt == 0) ? x0 : x2; gf = (mt == 0) ? x1 : x3;
                        gg2 = (mt == 0) ? c0 : c2; go = (mt == 0) ? c1 : c3;
                    }
                    int row = rg + mt * 8;
                    float ar0 = arr[mt].x, ar1 = arr[mt].y;
                    gi += ar0 * mA.x + ar1 * mB.x + bv.x;
                    gf += ar0 * mA.y + ar1 * mB.y + bv.y;
                    gg2 += ar0 * mA.z + ar1 * mB.z + bv.z;
                    go += ar0 * mA.w + ar1 * mB.w + bv.w;
                    float cold = g_c[u * BN + row];
                    float rf = __expf(-gf);
                    float ri = __expf(-gi);
                    float rg2 = __expf(-2.f * gg2);
                    float cn = __fdividef(cold, 1.f + rf)
                             + __fdividef(1.f - rg2, (1.f + ri) * (1.f + rg2));
                    float ro = __expf(-go);
                    float rc = __expf(-2.f * cn);
                    float es = __expf(pgr[mt].x * wga + pgr[mt].y * wgb + bgu - glr[mt]);
                    float hh = __fdividef(es * (1.f - rc), (1.f + ro) * (1.f + rc));
                    g_c[u * BN + row] = cn;
                    g_hpre[u * BN + row] = hh;
                }
            }
            __syncthreads();
        }

        // =================== PHASE 2: GAT (all 512 threads, warp = group) ===================
        float (*As)[132] = reinterpret_cast<float(*)[132]>(sm + GAT_AS);
        float* Bs = reinterpret_cast<float*>(sm + GAT_BS);
        float (*xS)[68] = reinterpret_cast<float(*)[68]>(sm + GAT_XS);

        {   // layer 1: hpre @ W1 ; lane owns 2 cols
            float acc[8][2];
#pragma unroll
            for (int i = 0; i < 8; i++) { acc[i][0] = 0.f; acc[i][1] = 0.f; }

            for (int kc = 0; kc < 4; kc++) {
                int k0 = kc * 32;
                __syncthreads();
#pragma unroll
                for (int it = 0; it < 2; it++) {
                    int idx = it * 512 + tid;
                    int k = idx >> 5, rq = idx & 31;
                    *reinterpret_cast<float4*>(&As[k][rq * 4]) =
                        *reinterpret_cast<const float4*>(&g_hpre[(k0 + k) * BN + m0 + rq * 4]);
                }
                {
                    int k = tid >> 4, qq = tid & 15;
                    *reinterpret_cast<float4*>(&Bs[k * 64 + qq * 4]) =
                        *reinterpret_cast<const float4*>(&g_W1[(k0 + k) * 64 + qq * 4]);
                }
                __syncthreads();
#pragma unroll
                for (int k = 0; k < 32; k++) {
                    float4 a0 = *reinterpret_cast<const float4*>(&As[k][w * 8]);
                    float4 a1 = *reinterpret_cast<const float4*>(&As[k][w * 8 + 4]);
                    float2 b = *reinterpret_cast<const float2*>(&Bs[k * 64 + lane * 2]);
                    float av[8] = {a0.x, a0.y, a0.z, a0.w, a1.x, a1.y, a1.z, a1.w};
#pragma unroll
                    for (int i = 0; i < 8; i++) {
                        acc[i][0] += av[i] * b.x;
                        acc[i][1] += av[i] * b.y;
                    }
                }
            }

            int hd = lane >> 3;
            int fcol = (lane * 2) & 15;
            float as0 = a_src1[hd * 16 + fcol], as1 = a_src1[hd * 16 + fcol + 1];
            float ad0 = a_dst1[hd * 16 + fcol], ad1 = a_dst1[hd * 16 + fcol + 1];
            float b10 = bias1[fcol], b11 = bias1[fcol + 1];

            float src[8], dst[8];
#pragma unroll
            for (int n = 0; n < 8; n++) {
                src[n] = acc[n][0] * as0 + acc[n][1] * as1;
                dst[n] = acc[n][0] * ad0 + acc[n][1] * ad1;
            }
#pragma unroll
            for (int off = 1; off <= 4; off <<= 1) {
#pragma unroll
                for (int n = 0; n < 8; n++) {
                    src[n] += __shfl_xor_sync(0xffffffffu, src[n], off);
                    dst[n] += __shfl_xor_sync(0xffffffffu, dst[n], off);
                }
            }
            __syncthreads();
#pragma unroll
            for (int n = 0; n < 8; n++) {
                float e[8], mx = -1e30f;
#pragma unroll
                for (int m = 0; m < 8; m++) {
                    float z = src[n] + dst[m];
                    z = (z >= 0.f) ? z : 0.2f * z;
                    e[m] = z;
                    mx = fmaxf(mx, z);
                }
                float s = 0.f;
#pragma unroll
                for (int m = 0; m < 8; m++) { e[m] = __expf(e[m] - mx); s += e[m]; }
                float inv = __fdividef(1.f, s);
                float o0 = 0.f, o1 = 0.f;
#pragma unroll
                for (int m = 0; m < 8; m++) {
                    float wgt = e[m] * inv;
                    o0 += wgt * acc[m][0];
                    o1 += wgt * acc[m][1];
                }
                o0 += b10;
                o1 += b11;
                o0 = (o0 > 0.f) ? o0 : (__expf(o0) - 1.f);
                o1 = (o1 > 0.f) ? o1 : (__expf(o1) - 1.f);
                *reinterpret_cast<float2*>(&xS[w * 8 + n][lane * 2]) = make_float2(o0, o1);
            }
        }
        __syncthreads();

        {   // layer 2: xS @ w2 ; lane owns 4 cols
            float acc[8][4];
#pragma unroll
            for (int i = 0; i < 8; i++)
#pragma unroll
                for (int j = 0; j < 4; j++) acc[i][j] = 0.f;

            for (int kc = 0; kc < 2; kc++) {
                int k0 = kc * 32;
                __syncthreads();
#pragma unroll
                for (int it = 0; it < 2; it++) {
                    int idx = it * 512 + tid;
                    int k = idx >> 5, qq = idx & 31;
                    *reinterpret_cast<float4*>(&Bs[k * 128 + qq * 4]) =
                        *reinterpret_cast<const float4*>(&w2[(k0 + k) * 128 + qq * 4]);
                }
                __syncthreads();
#pragma unroll
                for (int k = 0; k < 32; k++) {
                    float4 b = *reinterpret_cast<const float4*>(&Bs[k * 128 + lane * 4]);
                    float bw[4] = {b.x, b.y, b.z, b.w};
#pragma unroll
                    for (int i = 0; i < 8; i++) {
                        float av = xS[w * 8 + i][k0 + k];
#pragma unroll
                        for (int j = 0; j < 4; j++) acc[i][j] += av * bw[j];
                    }
                }
            }

            int o0c = lane * 4;
            float asv[4], adv[4], b2v[4], wp0[4], wp1[4];
#pragma unroll
            for (int j = 0; j < 4; j++) {
                asv[j] = a_src2[o0c + j];
                adv[j] = a_dst2[o0c + j];
                b2v[j] = bias2[o0c + j];
                wp0[j] = W_pos[(o0c + j) * 2 + 0];
                wp1[j] = W_pos[(o0c + j) * 2 + 1];
            }

            float src[8], dst[8];
#pragma unroll
            for (int n = 0; n < 8; n++) {
                float ps = 0.f, pd = 0.f;
#pragma unroll
                for (int j = 0; j < 4; j++) { ps += acc[n][j] * asv[j]; pd += acc[n][j] * adv[j]; }
                src[n] = ps; dst[n] = pd;
            }
#pragma unroll
            for (int off = 1; off <= 16; off <<= 1) {
#pragma unroll
                for (int n = 0; n < 8; n++) {
                    src[n] += __shfl_xor_sync(0xffffffffu, src[n], off);
                    dst[n] += __shfl_xor_sync(0xffffffffu, dst[n], off);
                }
            }
#pragma unroll
            for (int n = 0; n < 8; n++) {
                int row = m0 + w * 8 + n;
                float e[8], mx = -1e30f;
#pragma unroll
                for (int m = 0; m < 8; m++) {
                    float z = src[n] + dst[m];
                    z = (z >= 0.f) ? z : 0.2f * z;
                    e[m] = z;
                    mx = fmaxf(mx, z);
                }
                float s = 0.f;
#pragma unroll
                for (int m = 0; m < 8; m++) { e[m] = __expf(e[m] - mx); s += e[m]; }
                float inv = __fdividef(1.f, s);
                float o[4];
#pragma unroll
                for (int j = 0; j < 4; j++) o[j] = b2v[j];
#pragma unroll
                for (int m = 0; m < 8; m++) {
                    float wgt = e[m] * inv;
#pragma unroll
                    for (int j = 0; j < 4; j++) o[j] += wgt * acc[m][j];
                }
                *reinterpret_cast<float4*>(&g_h[row * 128 + o0c]) = make_float4(o[0], o[1], o[2], o[3]);
                float p0 = 0.f, p1 = 0.f;
#pragma unroll
                for (int j = 0; j < 4; j++) { p0 += o[j] * wp0[j]; p1 += o[j] * wp1[j]; }
#pragma unroll
                for (int off = 1; off <= 16; off <<= 1) {
                    p0 += __shfl_xor_sync(0xffffffffu, p0, off);
                    p1 += __shfl_xor_sync(0xffffffffu, p1, off);
                }
                if (lane == 0) {
                    out[(t * BN + row) * 2 + 0] = p0 + b_pos[0];
                    out[(t * BN + row) * 2 + 1] = p1 + b_pos[1];
                }
            }
        }
        __syncthreads();   // g_h written; smem free for next step's lstm
    }
}

extern "C" void kernel_launch(void* const* d_in, const int* in_sizes, int n_in,
                              void* d_out, int out_size) {
    const float* action_real = (const float*)d_in[0];
    const float* h0          = (const float*)d_in[1];
    const float* pred_goal   = (const float*)d_in[2];
    const float* W_emb  = (const float*)d_in[5];
    const float* b_emb  = (const float*)d_in[6];
    const float* W_ih   = (const float*)d_in[7];
    const float* W_hh   = (const float*)d_in[8];
    const float* b_ih   = (const float*)d_in[9];
    const float* b_hh   = (const float*)d_in[10];
    const float* W_goal = (const float*)d_in[11];
    const float* b_goal = (const float*)d_in[12];
    const float* w1     = (const float*)d_in[13];
    const float* a_src1 = (const float*)d_in[14];
    const float* a_dst1 = (const float*)d_in[15];
    const float* bias1  = (const float*)d_in[16];
    const float* w2     = (const float*)d_in[17];
    const float* a_src2 = (const float*)d_in[18];
    const float* a_dst2 = (const float*)d_in[19];
    const float* bias2  = (const float*)d_in[20];
    const float* W_pos  = (const float*)d_in[21];
    const float* b_pos  = (const float*)d_in[22];
    float* out = (float*)d_out;

    cudaFuncSetAttribute(mono_kernel, cudaFuncAttributeMaxDynamicSharedMemorySize, MONO_SMEM);

    setup_kernel<<<256, 256>>>(W_emb, b_emb, W_ih, W_hh, b_ih, b_hh, w1);
    init_kernel<<<(BN * HN + 255) / 256, 256>>>(h0);
    gls_kernel<<<(PREDN * BN * 32 + 255) / 256, 256>>>(pred_goal, W_goal, b_goal);

    mono_kernel<<<128, 512, MONO_SMEM>>>(action_real, pred_goal, W_goal, b_goal,
                                         a_src1, a_dst1, bias1, w2, a_src2, a_dst2,
                                         bias2, W_pos, b_pos, out);
}

// round 17
// speedup vs baseline: 1.2637x; 1.1028x over previous
#include <cuda_runtime.h>
#include <cuda_bf16.h>
#include <cstdint>

#define BN 16384
#define HN 128
#define PREDN 12

__device__ __forceinline__ uint32_t smem_u32(const void* p) {
    uint32_t a;
    asm("{ .reg .u64 t; cvta.to.shared.u64 t, %1; cvt.u32.u64 %0, t; }" : "=r"(a) : "l"(p));
    return a;
}

// swizzled byte offset, [128 rows][128 cols] bf16 tile
__device__ __forceinline__ int blk_off(int r, int c) {
    int boff = ((r >> 3) + (c >> 6) * 16) * 1024 + (r & 7) * 128 + (c & 63) * 2;
    return boff ^ ((boff >> 3) & 0x70);
}
// [64 rows][128 cols] bf16 tile
__device__ __forceinline__ int blk64(int r, int c) {
    int boff = ((r >> 3) + (c >> 6) * 8) * 1024 + (r & 7) * 128 + (c & 63) * 2;
    return boff ^ ((boff >> 3) & 0x70);
}
// [128 rows][64 cols] bf16 tile
__device__ __forceinline__ int blk128x64(int r, int c) {
    int boff = (r >> 3) * 1024 + (r & 7) * 128 + (c & 63) * 2;
    return boff ^ ((boff >> 3) & 0x70);
}

__device__ __forceinline__ void ldsm4(uint32_t* r, uint32_t addr) {
    asm volatile("ldmatrix.sync.aligned.m8n8.x4.shared.b16 {%0,%1,%2,%3}, [%4];"
                 : "=r"(r[0]), "=r"(r[1]), "=r"(r[2]), "=r"(r[3]) : "r"(addr));
}
__device__ __forceinline__ void ldsm4t(uint32_t* r, uint32_t addr) {
    asm volatile("ldmatrix.sync.aligned.m8n8.x4.trans.shared.b16 {%0,%1,%2,%3}, [%4];"
                 : "=r"(r[0]), "=r"(r[1]), "=r"(r[2]), "=r"(r[3]) : "r"(addr));
}
__device__ __forceinline__ void mma16816(float* c, const uint32_t* a, const uint32_t* b) {
    asm volatile(
        "mma.sync.aligned.m16n8k16.row.col.f32.bf16.bf16.f32 "
        "{%0,%1,%2,%3}, {%4,%5,%6,%7}, {%8,%9}, {%0,%1,%2,%3};"
        : "+f"(c[0]), "+f"(c[1]), "+f"(c[2]), "+f"(c[3])
        : "r"(a[0]), "r"(a[1]), "r"(a[2]), "r"(a[3]), "r"(b[0]), "r"(b[1]));
}
#define CP_ASYNC16(dst, src) \
    asm volatile("cp.async.cg.shared.global [%0], [%1], 16;" :: "r"(dst), "l"(src))
#define CP_COMMIT asm volatile("cp.async.commit_group;" ::: "memory")
#define CP_WAIT1 asm volatile("cp.async.wait_group 1;" ::: "memory")
#define CP_WAIT0 asm volatile("cp.async.wait_group 0;" ::: "memory")

// ==================== device scratch ====================
__device__ __align__(16) unsigned short g_WpHi[4][16384];
__device__ __align__(16) unsigned short g_WpLo[4][16384];
__device__ __align__(16) unsigned short g_W1Hi[8192];   // W1 B-operand [n64][k128] swizzled
__device__ __align__(16) unsigned short g_W1Lo[8192];
__device__ __align__(16) unsigned short g_W2Hi[8192];   // w2 B-operand [n128][k64] swizzled
__device__ __align__(16) unsigned short g_W2Lo[8192];
__device__ float g_Mc[2 * 512];
__device__ float g_bv[512];
__device__ float g_h[BN * HN];      // row-major
__device__ float g_c[BN * HN];      // column-major [u][BN]
__device__ float g_hpre[BN * HN];   // column-major [k][BN]
__device__ float g_gls[PREDN * BN];

// ==================== setup ====================
__global__ void setup_kernel(const float* __restrict__ W_emb, const float* __restrict__ b_emb,
                             const float* __restrict__ W_ih, const float* __restrict__ W_hh,
                             const float* __restrict__ b_ih, const float* __restrict__ b_hh,
                             const float* __restrict__ w1, const float* __restrict__ w2) {
    int idx = blockIdx.x * 256 + threadIdx.x;
    if (idx < 128 * 512) {
        int k = idx >> 9, n = idx & 511;
        int u = n >> 2, g = n & 3;
        float v = W_hh[(g * 128 + u) * 128 + k];
        __nv_bfloat16 bh = __float2bfloat16(v);
        __nv_bfloat16 bl = __float2bfloat16(v - __bfloat162float(bh));
        int chunk = n >> 7, nr = n & 127;
        int sw = blk_off(nr, k);
        g_WpHi[chunk][sw >> 1] = __bfloat16_as_ushort(bh);
        g_WpLo[chunk][sw >> 1] = __bfloat16_as_ushort(bl);
    }
    if (idx < 8192) {   // W1: n = idx&63, k = idx>>6
        int n = idx & 63, k = idx >> 6;
        float v = w1[((n >> 4) * 128 + k) * 16 + (n & 15)];
        __nv_bfloat16 bh = __float2bfloat16(v);
        __nv_bfloat16 bl = __float2bfloat16(v - __bfloat162float(bh));
        int sw = blk64(n, k);
        g_W1Hi[sw >> 1] = __bfloat16_as_ushort(bh);
        g_W1Lo[sw >> 1] = __bfloat16_as_ushort(bl);
    }
    if (idx < 8192) {   // w2: n = idx&127, k = idx>>7
        int n = idx & 127, k = idx >> 7;
        float v = w2[k * 128 + n];
        __nv_bfloat16 bh = __float2bfloat16(v);
        __nv_bfloat16 bl = __float2bfloat16(v - __bfloat162float(bh));
        int sw = blk128x64(n, k);
        g_W2Hi[sw >> 1] = __bfloat16_as_ushort(bh);
        g_W2Lo[sw >> 1] = __bfloat16_as_ushort(bl);
    }
    if (idx < 512) {
        int n = idx;
        int u = n >> 2, g = n & 3;
        int row = g * 128 + u;
        float m0 = 0.f, m1 = 0.f, bb = 0.f;
        for (int e = 0; e < 64; e++) {
            float wih = W_ih[row * 64 + e];
            m0 += W_emb[e] * wih;
            m1 += W_emb[64 + e] * wih;
            bb += b_emb[e] * wih;
        }
        g_Mc[n] = m0;
        g_Mc[512 + n] = m1;
        g_bv[n] = bb + b_ih[row] + b_hh[row];
    }
}

__global__ void init_kernel(const float* __restrict__ h0) {
    int i = blockIdx.x * 256 + threadIdx.x;
    if (i < BN * HN) { g_h[i] = h0[i]; g_c[i] = 0.f; }
}

__global__ void gls_kernel(const float* __restrict__ pred_goal, const float* __restrict__ W_goal,
                           const float* __restrict__ b_goal) {
    int gw = (blockIdx.x * 256 + threadIdx.x) >> 5;
    int lane = threadIdx.x & 31;
    if (gw >= PREDN * BN) return;
    float pg0 = pred_goal[gw * 2 + 0], pg1 = pred_goal[gw * 2 + 1];
    float z[4];
    float m = -1e30f;
#pragma unroll
    for (int q = 0; q < 4; q++) {
        int u = lane + q * 32;
        z[q] = pg0 * W_goal[u] + pg1 * W_goal[128 + u] + b_goal[u];
        m = fmaxf(m, z[q]);
    }
#pragma unroll
    for (int s = 16; s > 0; s >>= 1) m = fmaxf(m, __shfl_xor_sync(0xffffffffu, m, s));
    float sum = 0.f;
#pragma unroll
    for (int q = 0; q < 4; q++) sum += __expf(z[q] - m);
#pragma unroll
    for (int s = 16; s > 0; s >>= 1) sum += __shfl_xor_sync(0xffffffffu, sum, s);
    if (lane == 0) g_gls[gw] = m + __logf(sum);
}

// ==================== PERSISTENT mono kernel ====================
#define SM_AHI 0
#define SM_ALO 32768
#define SM_B0  65536
#define MONO_SMEM 196608
// gat regions (barrier-protected aliasing of the lstm regions)
#define GA_HI 0
#define GA_LO 32768
#define GB    65536          // +16384 for lo
#define GD    98304          // layer1 D fp32 [128][68]; later layer2 D [128][132]
#define GX_HI 133120         // x bf16 [k64][m128]
#define GX_LO 149504

__global__ __launch_bounds__(512, 1) void mono_kernel(
        const float* __restrict__ action_real,
        const float* __restrict__ pred_goal,
        const float* __restrict__ W_goal,
        const float* __restrict__ b_goal,
        const float* __restrict__ a_src1,
        const float* __restrict__ a_dst1,
        const float* __restrict__ bias1,
        const float* __restrict__ a_src2,
        const float* __restrict__ a_dst2,
        const float* __restrict__ bias2,
        const float* __restrict__ W_pos,
        const float* __restrict__ b_pos,
        float* __restrict__ out) {
    extern __shared__ __align__(1024) char sm[];
    uint32_t sb = smem_u32(sm);
    int tid = threadIdx.x;
    int w = tid >> 5, lane = tid & 31;
    int m0 = blockIdx.x * 128;

    int g = lane >> 2, q = lane & 3;
    int parity = q & 1, uloc = q >> 1;
    int wm = w >> 1, wn = w & 1;
    int rg = m0 + wm * 16 + g;
    int a_row = lane & 15;
    int a_khalf = (lane >> 4) * 8;
    int b_nloc = wn * 64 + (lane >> 4) * 8 + (lane & 7);
    int b_khalf = ((lane >> 3) & 1) * 8;
    // gat mma lane constants
    int aw_m = wm * 16 + ((lane >> 3) & 1) * 8;
    int aw_k = ((lane >> 4) & 1) * 8 + (lane & 7);
    int gb_n = (lane >> 4) * 8 + (lane & 7);
    int gb_k = ((lane >> 3) & 1) * 8;

    for (int t = 0; t < PREDN; t++) {
        // =================== PHASE 1: LSTM (unchanged, proven) ===================
        {
            const char* srcH = (const char*)g_WpHi[0];
            const char* srcL = (const char*)g_WpLo[0];
            uint32_t dH = sb + SM_B0;
            uint32_t dL = dH + 32768;
#pragma unroll
            for (int it = 0; it < 4; it++) {
                int off = (it * 512 + tid) * 16;
                CP_ASYNC16(dH + off, srcH + off);
                CP_ASYNC16(dL + off, srcL + off);
            }
            CP_COMMIT;
        }
#pragma unroll
        for (int it = 0; it < 8; it++) {
            int idx = it * 512 + tid;
            int r = idx >> 5;
            int c4 = (idx & 31) * 4;
            float4 v = *reinterpret_cast<const float4*>(&g_h[(m0 + r) * 128 + c4]);
            float a[4] = {v.x, v.y, v.z, v.w};
            unsigned short hs[4], ls[4];
#pragma unroll
            for (int p = 0; p < 4; p++) {
                __nv_bfloat16 bh = __float2bfloat16(a[p]);
                __nv_bfloat16 bl = __float2bfloat16(a[p] - __bfloat162float(bh));
                hs[p] = __bfloat16_as_ushort(bh);
                ls[p] = __bfloat16_as_ushort(bl);
            }
            int sw = blk_off(r, c4);
            *reinterpret_cast<uint2*>(sm + SM_AHI + sw) =
                make_uint2((uint32_t)hs[0] | ((uint32_t)hs[1] << 16),
                           (uint32_t)hs[2] | ((uint32_t)hs[3] << 16));
            *reinterpret_cast<uint2*>(sm + SM_ALO + sw) =
                make_uint2((uint32_t)ls[0] | ((uint32_t)ls[1] << 16),
                           (uint32_t)ls[2] | ((uint32_t)ls[3] << 16));
        }

        float2 arr[2], pgr[2];
        float glr[2];
#pragma unroll
        for (int mt = 0; mt < 2; mt++) {
            int row = rg + mt * 8;
            arr[mt] = *reinterpret_cast<const float2*>(&action_real[((8 + t) * BN + row) * 2]);
            pgr[mt] = *reinterpret_cast<const float2*>(&pred_goal[(t * BN + row) * 2]);
            glr[mt] = g_gls[t * BN + row];
        }

        for (int nc = 0; nc < 4; nc++) {
            uint32_t bbase = sb + SM_B0 + (nc & 1) * 65536;
            if (nc < 3) {
                const char* srcH = (const char*)g_WpHi[nc + 1];
                const char* srcL = (const char*)g_WpLo[nc + 1];
                uint32_t dH = sb + SM_B0 + (((nc + 1) & 1) * 65536);
                uint32_t dL = dH + 32768;
#pragma unroll
                for (int it = 0; it < 4; it++) {
                    int off = (it * 512 + tid) * 16;
                    CP_ASYNC16(dH + off, srcH + off);
                    CP_ASYNC16(dL + off, srcL + off);
                }
                CP_COMMIT;
                CP_WAIT1;
            } else {
                CP_WAIT0;
            }
            __syncthreads();

            float acc[8][4];
#pragma unroll
            for (int j = 0; j < 8; j++)
#pragma unroll
                for (int p = 0; p < 4; p++) acc[j][p] = 0.f;

#pragma unroll
            for (int ks = 0; ks < 8; ks++) {
                int kc = ks * 16;
                uint32_t ahi[4], alo[4];
                uint32_t ad = sb + SM_AHI + blk_off(wm * 16 + a_row, kc + a_khalf);
                ldsm4(ahi, ad);
                ldsm4(alo, ad + 32768);
                uint32_t bhi[4][4], blo[4][4];
#pragma unroll
                for (int pr = 0; pr < 4; pr++) {
                    uint32_t bd = bbase + blk_off(b_nloc + pr * 16, kc + b_khalf);
                    ldsm4(bhi[pr], bd);
                    ldsm4(blo[pr], bd + 32768);
                }
#pragma unroll
                for (int nt = 0; nt < 8; nt++) {
                    int pr = nt >> 1, hf = (nt & 1) * 2;
                    mma16816(acc[nt], ahi, &bhi[pr][hf]);
                    mma16816(acc[nt], ahi, &blo[pr][hf]);
                    mma16816(acc[nt], alo, &bhi[pr][hf]);
                }
            }

#pragma unroll
            for (int nt = 0; nt < 8; nt++) {
                int u = nc * 32 + wn * 16 + nt * 2 + uloc;
                int n4 = u * 4;
                float4 mA = *reinterpret_cast<const float4*>(&g_Mc[n4]);
                float4 mB = *reinterpret_cast<const float4*>(&g_Mc[512 + n4]);
                float4 bv = *reinterpret_cast<const float4*>(&g_bv[n4]);
                float wga = W_goal[u], wgb = W_goal[128 + u], bgu = b_goal[u];
                float c0 = acc[nt][0], c1 = acc[nt][1], c2 = acc[nt][2], c3 = acc[nt][3];
                float x0 = __shfl_xor_sync(0xffffffffu, c0, 1);
                float x1 = __shfl_xor_sync(0xffffffffu, c1, 1);
                float x2 = __shfl_xor_sync(0xffffffffu, c2, 1);
                float x3 = __shfl_xor_sync(0xffffffffu, c3, 1);
#pragma unroll
                for (int mt = 0; mt < 2; mt++) {
                    float gi, gf, gg2, go;
                    if (parity == 0) {
                        gi = (mt == 0) ? c0 : c2; gf = (mt == 0) ? c1 : c3;
                        gg2 = (mt == 0) ? x0 : x2; go = (mt == 0) ? x1 : x3;
                    } else {
                        gi = (mt == 0) ? x0 : x2; gf = (mt == 0) ? x1 : x3;
                        gg2 = (mt == 0) ? c0 : c2; go = (mt == 0) ? c1 : c3;
                    }
                    int row = rg + mt * 8;
                    float ar0 = arr[mt].x, ar1 = arr[mt].y;
                    gi += ar0 * mA.x + ar1 * mB.x + bv.x;
                    gf += ar0 * mA.y + ar1 * mB.y + bv.y;
                    gg2 += ar0 * mA.z + ar1 * mB.z + bv.z;
                    go += ar0 * mA.w + ar1 * mB.w + bv.w;
                    float cold = g_c[u * BN + row];
                    float rf = __expf(-gf);
                    float ri = __expf(-gi);
                    float rg2 = __expf(-2.f * gg2);
                    float cn = __fdividef(cold, 1.f + rf)
                             + __fdividef(1.f - rg2, (1.f + ri) * (1.f + rg2));
                    float ro = __expf(-go);
                    float rc = __expf(-2.f * cn);
                    float es = __expf(pgr[mt].x * wga + pgr[mt].y * wgb + bgu - glr[mt]);
                    float hh = __fdividef(es * (1.f - rc), (1.f + ro) * (1.f + rc));
                    g_c[u * BN + row] = cn;
                    g_hpre[u * BN + row] = hh;
                }
            }
            __syncthreads();
        }

        // =================== PHASE 2: GAT on tensor cores ===================
        // (a) hpre -> GA bf16 hi/lo (K-major [k][m]); W1 -> GB
#pragma unroll
        for (int it = 0; it < 8; it++) {
            int idx = it * 512 + tid;
            int k = idx >> 5, r4 = (idx & 31) * 4;
            float4 v = *reinterpret_cast<const float4*>(&g_hpre[k * BN + m0 + r4]);
            float a[4] = {v.x, v.y, v.z, v.w};
            unsigned short hs[4], ls[4];
#pragma unroll
            for (int p = 0; p < 4; p++) {
                __nv_bfloat16 bh = __float2bfloat16(a[p]);
                __nv_bfloat16 bl = __float2bfloat16(a[p] - __bfloat162float(bh));
                hs[p] = __bfloat16_as_ushort(bh);
                ls[p] = __bfloat16_as_ushort(bl);
            }
            int sw = blk_off(k, r4);
            *reinterpret_cast<uint2*>(sm + GA_HI + sw) =
                make_uint2((uint32_t)hs[0] | ((uint32_t)hs[1] << 16),
                           (uint32_t)hs[2] | ((uint32_t)hs[3] << 16));
            *reinterpret_cast<uint2*>(sm + GA_LO + sw) =
                make_uint2((uint32_t)ls[0] | ((uint32_t)ls[1] << 16),
                           (uint32_t)ls[2] | ((uint32_t)ls[3] << 16));
        }
#pragma unroll
        for (int it = 0; it < 2; it++) {
            int i = it * 512 + tid;
            reinterpret_cast<uint4*>(sm + GB)[i] = reinterpret_cast<const uint4*>(g_W1Hi)[i];
            reinterpret_cast<uint4*>(sm + GB + 16384)[i] = reinterpret_cast<const uint4*>(g_W1Lo)[i];
        }
        __syncthreads();

        float* GDp = reinterpret_cast<float*>(sm + GD);

        // (b) layer-1 MMA: warp (wm, wn) -> rows wm*16, cols wn*32
        {
            float acc1[4][4];
#pragma unroll
            for (int i = 0; i < 4; i++)
#pragma unroll
                for (int j = 0; j < 4; j++) acc1[i][j] = 0.f;
#pragma unroll
            for (int ks = 0; ks < 8; ks++) {
                uint32_t ahi[4], alo[4];
                uint32_t aad = sb + GA_HI + blk_off(ks * 16 + aw_k, aw_m);
                ldsm4t(ahi, aad);
                ldsm4t(alo, aad + 32768);
                uint32_t bhi[2][4], blo[2][4];
#pragma unroll
                for (int pp = 0; pp < 2; pp++) {
                    uint32_t bad = sb + GB + blk64((wn * 2 + pp) * 16 + gb_n, ks * 16 + gb_k);
                    ldsm4(bhi[pp], bad);
                    ldsm4(blo[pp], bad + 16384);
                }
#pragma unroll
                for (int nt = 0; nt < 4; nt++) {
                    int pp = nt >> 1, hf = (nt & 1) * 2;
                    mma16816(acc1[nt], ahi, &bhi[pp][hf]);
                    mma16816(acc1[nt], ahi, &blo[pp][hf]);
                    mma16816(acc1[nt], alo, &bhi[pp][hf]);
                }
            }
#pragma unroll
            for (int nt = 0; nt < 4; nt++) {
                int col = wn * 32 + nt * 8 + q * 2;
                *reinterpret_cast<float2*>(&GDp[(wm * 16 + g) * 68 + col]) =
                    make_float2(acc1[nt][0], acc1[nt][1]);
                *reinterpret_cast<float2*>(&GDp[(wm * 16 + 8 + g) * 68 + col]) =
                    make_float2(acc1[nt][2], acc1[nt][3]);
            }
        }
        __syncthreads();

        // (c) attention 1 (warp = group, lane = 2 cols), x -> GX bf16; w2 -> GB
#pragma unroll
        for (int it = 0; it < 2; it++) {
            int i = it * 512 + tid;
            reinterpret_cast<uint4*>(sm + GB)[i] = reinterpret_cast<const uint4*>(g_W2Hi)[i];
            reinterpret_cast<uint4*>(sm + GB + 16384)[i] = reinterpret_cast<const uint4*>(g_W2Lo)[i];
        }
        {
            float a1[8][2];
#pragma unroll
            for (int n = 0; n < 8; n++) {
                float2 tv = *reinterpret_cast<const float2*>(&GDp[(w * 8 + n) * 68 + lane * 2]);
                a1[n][0] = tv.x;
                a1[n][1] = tv.y;
            }
            int hd = lane >> 3;
            int fcol = (lane * 2) & 15;
            float as0 = a_src1[hd * 16 + fcol], as1 = a_src1[hd * 16 + fcol + 1];
            float ad0 = a_dst1[hd * 16 + fcol], ad1 = a_dst1[hd * 16 + fcol + 1];
            float b10 = bias1[fcol], b11 = bias1[fcol + 1];

            float srcv[8], dstv[8];
#pragma unroll
            for (int n = 0; n < 8; n++) {
                srcv[n] = a1[n][0] * as0 + a1[n][1] * as1;
                dstv[n] = a1[n][0] * ad0 + a1[n][1] * ad1;
            }
#pragma unroll
            for (int off = 1; off <= 4; off <<= 1) {
#pragma unroll
                for (int n = 0; n < 8; n++) {
                    srcv[n] += __shfl_xor_sync(0xffffffffu, srcv[n], off);
                    dstv[n] += __shfl_xor_sync(0xffffffffu, dstv[n], off);
                }
            }
            unsigned short xh[2][8], xl[2][8];
#pragma unroll
            for (int n = 0; n < 8; n++) {
                float e[8], mx = -1e30f;
#pragma unroll
                for (int m = 0; m < 8; m++) {
                    float z = srcv[n] + dstv[m];
                    z = (z >= 0.f) ? z : 0.2f * z;
                    e[m] = z;
                    mx = fmaxf(mx, z);
                }
                float s = 0.f;
#pragma unroll
                for (int m = 0; m < 8; m++) { e[m] = __expf(e[m] - mx); s += e[m]; }
                float inv = __fdividef(1.f, s);
                float o0 = 0.f, o1 = 0.f;
#pragma unroll
                for (int m = 0; m < 8; m++) {
                    float wgt = e[m] * inv;
                    o0 += wgt * a1[m][0];
                    o1 += wgt * a1[m][1];
                }
                o0 += b10;
                o1 += b11;
                o0 = (o0 > 0.f) ? o0 : (__expf(o0) - 1.f);
                o1 = (o1 > 0.f) ? o1 : (__expf(o1) - 1.f);
                __nv_bfloat16 h0b = __float2bfloat16(o0);
                __nv_bfloat16 l0b = __float2bfloat16(o0 - __bfloat162float(h0b));
                __nv_bfloat16 h1b = __float2bfloat16(o1);
                __nv_bfloat16 l1b = __float2bfloat16(o1 - __bfloat162float(h1b));
                xh[0][n] = __bfloat16_as_ushort(h0b);
                xl[0][n] = __bfloat16_as_ushort(l0b);
                xh[1][n] = __bfloat16_as_ushort(h1b);
                xl[1][n] = __bfloat16_as_ushort(l1b);
            }
#pragma unroll
            for (int cc = 0; cc < 2; cc++) {
                int sw = blk64(lane * 2 + cc, w * 8);
                *reinterpret_cast<uint4*>(sm + GX_HI + sw) =
                    make_uint4((uint32_t)xh[cc][0] | ((uint32_t)xh[cc][1] << 16),
                               (uint32_t)xh[cc][2] | ((uint32_t)xh[cc][3] << 16),
                               (uint32_t)xh[cc][4] | ((uint32_t)xh[cc][5] << 16),
                               (uint32_t)xh[cc][6] | ((uint32_t)xh[cc][7] << 16));
                *reinterpret_cast<uint4*>(sm + GX_LO + sw) =
                    make_uint4((uint32_t)xl[cc][0] | ((uint32_t)xl[cc][1] << 16),
                               (uint32_t)xl[cc][2] | ((uint32_t)xl[cc][3] << 16),
                               (uint32_t)xl[cc][4] | ((uint32_t)xl[cc][5] << 16),
                               (uint32_t)xl[cc][6] | ((uint32_t)xl[cc][7] << 16));
            }
        }
        __syncthreads();

        // (d) layer-2 MMA: warp (wm, wn) -> rows wm*16, cols wn*64
        float acc2[8][4];
#pragma unroll
        for (int i = 0; i < 8; i++)
#pragma unroll
            for (int j = 0; j < 4; j++) acc2[i][j] = 0.f;
#pragma unroll
        for (int ks = 0; ks < 4; ks++) {
            uint32_t ahi[4], alo[4];
            uint32_t aad = sb + GX_HI + blk64(ks * 16 + aw_k, aw_m);
            ldsm4t(ahi, aad);
            ldsm4t(alo, aad + 16384);
            uint32_t bhi[4][4], blo[4][4];
#pragma unroll
            for (int pp = 0; pp < 4; pp++) {
                uint32_t bad = sb + GB + blk128x64((wn * 4 + pp) * 16 + gb_n, ks * 16 + gb_k);
                ldsm4(bhi[pp], bad);
                ldsm4(blo[pp], bad + 16384);
            }
#pragma unroll
            for (int nt = 0; nt < 8; nt++) {
                int pp = nt >> 1, hf = (nt & 1) * 2;
                mma16816(acc2[nt], ahi, &bhi[pp][hf]);
                mma16816(acc2[nt], ahi, &blo[pp][hf]);
                mma16816(acc2[nt], alo, &bhi[pp][hf]);
            }
        }
        __syncthreads();   // all GX/GB reads done before D2 overwrites GX region
        float* GD2p = reinterpret_cast<float*>(sm + GD);   // pitch 132, 98304..165888
#pragma unroll
        for (int nt = 0; nt < 8; nt++) {
            int col = wn * 64 + nt * 8 + q * 2;
            *reinterpret_cast<float2*>(&GD2p[(wm * 16 + g) * 132 + col]) =
                make_float2(acc2[nt][0], acc2[nt][1]);
            *reinterpret_cast<float2*>(&GD2p[(wm * 16 + 8 + g) * 132 + col]) =
                make_float2(acc2[nt][2], acc2[nt][3]);
        }
        __syncthreads();

        // (e) final attention (warp = group, lane = 4 cols) + W_pos output
        {
            int o0c = lane * 4;
            float asv[4], adv[4], b2v[4], wp0[4], wp1[4];
#pragma unroll
            for (int j = 0; j < 4; j++) {
                asv[j] = a_src2[o0c + j];
                adv[j] = a_dst2[o0c + j];
                b2v[j] = bias2[o0c + j];
                wp0[j] = W_pos[(o0c + j) * 2 + 0];
                wp1[j] = W_pos[(o0c + j) * 2 + 1];
            }
            float a2[8][4];
#pragma unroll
            for (int n = 0; n < 8; n++) {
                float4 tv = *reinterpret_cast<const float4*>(&GD2p[(w * 8 + n) * 132 + o0c]);
                a2[n][0] = tv.x; a2[n][1] = tv.y; a2[n][2] = tv.z; a2[n][3] = tv.w;
            }
            float srcv[8], dstv[8];
#pragma unroll
            for (int n = 0; n < 8; n++) {
                float ps = 0.f, pd = 0.f;
#pragma unroll
                for (int j = 0; j < 4; j++) { ps += a2[n][j] * asv[j]; pd += a2[n][j] * adv[j]; }
                srcv[n] = ps; dstv[n] = pd;
            }
#pragma unroll
            for (int off = 1; off <= 16; off <<= 1) {
#pragma unroll
                for (int n = 0; n < 8; n++) {
                    srcv[n] += __shfl_xor_sync(0xffffffffu, srcv[n], off);
                    dstv[n] += __shfl_xor_sync(0xffffffffu, dstv[n], off);
                }
            }
#pragma unroll
            for (int n = 0; n < 8; n++) {
                int row = m0 + w * 8 + n;
                float e[8], mx = -1e30f;
#pragma unroll
                for (int m = 0; m < 8; m++) {
                    float z = srcv[n] + dstv[m];
                    z = (z >= 0.f) ? z : 0.2f * z;
                    e[m] = z;
                    mx = fmaxf(mx, z);
                }
                float s = 0.f;
#pragma unroll
                for (int m = 0; m < 8; m++) { e[m] = __expf(e[m] - mx); s += e[m]; }
                float inv = __fdividef(1.f, s);
                float o[4];
#pragma unroll
                for (int j = 0; j < 4; j++) o[j] = b2v[j];
#pragma unroll
                for (int m = 0; m < 8; m++) {
                    float wgt = e[m] * inv;
#pragma unroll
                    for (int j = 0; j < 4; j++) o[j] += wgt * a2[m][j];
                }
                *reinterpret_cast<float4*>(&g_h[row * 128 + o0c]) =
                    make_float4(o[0], o[1], o[2], o[3]);
                float p0 = 0.f, p1 = 0.f;
#pragma unroll
                for (int j = 0; j < 4; j++) { p0 += o[j] * wp0[j]; p1 += o[j] * wp1[j]; }
#pragma unroll
                for (int off = 1; off <= 16; off <<= 1) {
                    p0 += __shfl_xor_sync(0xffffffffu, p0, off);
                    p1 += __shfl_xor_sync(0xffffffffu, p1, off);
                }
                if (lane == 0) {
                    out[(t * BN + row) * 2 + 0] = p0 + b_pos[0];
                    out[(t * BN + row) * 2 + 1] = p1 + b_pos[1];
                }
            }
        }
        __syncthreads();   // end of step
    }
}

extern "C" void kernel_launch(void* const* d_in, const int* in_sizes, int n_in,
                              void* d_out, int out_size) {
    const float* action_real = (const float*)d_in[0];
    const float* h0          = (const float*)d_in[1];
    const float* pred_goal   = (const float*)d_in[2];
    const float* W_emb  = (const float*)d_in[5];
    const float* b_emb  = (const float*)d_in[6];
    const float* W_ih   = (const float*)d_in[7];
    const float* W_hh   = (const float*)d_in[8];
    const float* b_ih   = (const float*)d_in[9];
    const float* b_hh   = (const float*)d_in[10];
    const float* W_goal = (const float*)d_in[11];
    const float* b_goal = (const float*)d_in[12];
    const float* w1     = (const float*)d_in[13];
    const float* a_src1 = (const float*)d_in[14];
    const float* a_dst1 = (const float*)d_in[15];
    const float* bias1  = (const float*)d_in[16];
    const float* w2     = (const float*)d_in[17];
    const float* a_src2 = (const float*)d_in[18];
    const float* a_dst2 = (const float*)d_in[19];
    const float* bias2  = (const float*)d_in[20];
    const float* W_pos  = (const float*)d_in[21];
    const float* b_pos  = (const float*)d_in[22];
    float* out = (float*)d_out;

    cudaFuncSetAttribute(mono_kernel, cudaFuncAttributeMaxDynamicSharedMemorySize, MONO_SMEM);

    setup_kernel<<<256, 256>>>(W_emb, b_emb, W_ih, W_hh, b_ih, b_hh, w1, w2);
    init_kernel<<<(BN * HN + 255) / 256, 256>>>(h0);
    gls_kernel<<<(PREDN * BN * 32 + 255) / 256, 256>>>(pred_goal, W_goal, b_goal);

    mono_kernel<<<128, 512, MONO_SMEM>>>(action_real, pred_goal, W_goal, b_goal,
                                         a_src1, a_dst1, bias1, a_src2, a_dst2,
                                         bias2, W_pos, b_pos, out);
}